// round 1
// baseline (speedup 1.0000x reference)
#include <cuda_runtime.h>
#include <math.h>

// Problem constants
#define BN   4
#define CN   256
#define HWN  4096
#define DN   128          // INTER = C/2

// -------------------- scratch (device globals; no allocation) --------------------
__device__ float d_Q [BN * DN * HWN];   // theta, layout [b][i][n]
__device__ float d_Kx[BN * DN * HWN];   // phi,   layout [b][i][n]
__device__ float d_G [BN * HWN * DN];   // g,     layout [b][n][i]
__device__ float d_Y [BN * HWN * DN];   // attn output, layout [b][n][i]
__device__ float d_WY[BN * CN * HWN];   // W*y + b, layout [b][c][n]
__device__ float d_MEAN[CN];
__device__ float d_RSTD[CN];

// ============================================================================
// K1: fused 1x1-conv projections.
//   out[b,i,n] = sum_c x[b,c,n] * w[i,c] + bias[i]
// gridDim = (3 projections, HW/64 tiles, B). Block = 256 threads.
// Tile: 64 n x 128 i. theta/phi stored [i][n]; g stored [n][i] (for V reads).
// ============================================================================
__global__ void proj_kernel(const float* __restrict__ x,
                            const float* __restrict__ tw, const float* __restrict__ tb,
                            const float* __restrict__ pw, const float* __restrict__ pb,
                            const float* __restrict__ gw, const float* __restrict__ gb)
{
    const int p  = blockIdx.x;           // 0=theta, 1=phi, 2=g
    const int n0 = blockIdx.y * 64;
    const int b  = blockIdx.z;
    const float* w    = (p == 0) ? tw : (p == 1) ? pw : gw;
    const float* bias = (p == 0) ? tb : (p == 1) ? pb : gb;

    __shared__ float xs[32][68];    // xs[cc][nn]
    __shared__ float ws[32][132];   // ws[cc][ii], ii in 0..127

    const int tid = threadIdx.x;
    const int tx  = tid & 15;       // n-group: n = n0 + 4*tx + i
    const int ty  = tid >> 4;       // i-group: i = 8*ty + j

    float acc[4][8];
#pragma unroll
    for (int i = 0; i < 4; i++)
#pragma unroll
        for (int j = 0; j < 8; j++) acc[i][j] = 0.f;

    for (int c0 = 0; c0 < CN; c0 += 32) {
        // x tile: 32 c x 64 n (rows contiguous in global)
#pragma unroll
        for (int r = 0; r < 2; r++) {
            int idx = tid + r * 256;            // 0..511
            int cc  = idx >> 4, g = idx & 15;
            float4 v = *(const float4*)(x + ((size_t)b * CN + c0 + cc) * HWN + n0 + 4 * g);
            *(float4*)&xs[cc][4 * g] = v;
        }
        // weight tile transposed: w[ii][c0+cc] -> ws[cc][ii]
#pragma unroll
        for (int r = 0; r < 4; r++) {
            int idx = tid + r * 256;            // 0..1023
            int ii  = idx >> 3, cg = idx & 7;
            float4 v = *(const float4*)(w + (size_t)ii * CN + c0 + 4 * cg);
            ws[4 * cg + 0][ii] = v.x;
            ws[4 * cg + 1][ii] = v.y;
            ws[4 * cg + 2][ii] = v.z;
            ws[4 * cg + 3][ii] = v.w;
        }
        __syncthreads();
#pragma unroll 8
        for (int cc = 0; cc < 32; cc++) {
            float4 xv = *(float4*)&xs[cc][4 * tx];
            float4 w0 = *(float4*)&ws[cc][8 * ty];
            float4 w1 = *(float4*)&ws[cc][8 * ty + 4];
            float xr[4] = {xv.x, xv.y, xv.z, xv.w};
            float wr[8] = {w0.x, w0.y, w0.z, w0.w, w1.x, w1.y, w1.z, w1.w};
#pragma unroll
            for (int i = 0; i < 4; i++)
#pragma unroll
                for (int j = 0; j < 8; j++)
                    acc[i][j] += xr[i] * wr[j];
        }
        __syncthreads();
    }

    if (p < 2) {
        float* out = (p == 0) ? d_Q : d_Kx;     // [b][i][n]
#pragma unroll
        for (int j = 0; j < 8; j++) {
            int ii = 8 * ty + j;
            float bb = bias[ii];
            float4 v = make_float4(acc[0][j] + bb, acc[1][j] + bb,
                                   acc[2][j] + bb, acc[3][j] + bb);
            *(float4*)(out + ((size_t)b * DN + ii) * HWN + n0 + 4 * tx) = v;
        }
    } else {                                    // g -> [b][n][i]
        float b0 = bias[8 * ty + 0], b1 = bias[8 * ty + 1], b2 = bias[8 * ty + 2], b3 = bias[8 * ty + 3];
        float b4 = bias[8 * ty + 4], b5 = bias[8 * ty + 5], b6 = bias[8 * ty + 6], b7 = bias[8 * ty + 7];
#pragma unroll
        for (int i = 0; i < 4; i++) {
            int n = n0 + 4 * tx + i;
            float4 v0 = make_float4(acc[i][0] + b0, acc[i][1] + b1, acc[i][2] + b2, acc[i][3] + b3);
            float4 v1 = make_float4(acc[i][4] + b4, acc[i][5] + b5, acc[i][6] + b6, acc[i][7] + b7);
            *(float4*)(d_G + ((size_t)b * HWN + n) * DN + 8 * ty)     = v0;
            *(float4*)(d_G + ((size_t)b * HWN + n) * DN + 8 * ty + 4) = v1;
        }
    }
}

// ============================================================================
// K2: fused attention (flash style, fp32).
//   f[n,m] = sum_k Q[k,n]*K[k,m];  attn = softmax_m(f);  Y[n,:] = attn @ V
// grid = (HW/64, B), block = 256, dynamic SMEM ~121.6 KB -> 1 CTA/SM.
// ============================================================================
__global__ void attn_kernel()
{
    extern __shared__ float sm[];
    float* qs   = sm;                 // [k][n]  128 x 68
    float* ks   = qs + 128 * 68;      // [k][m]  128 x 68
    float* vs   = ks + 128 * 68;      // [m][d]   64 x 132
    float* ps   = vs + 64 * 132;      // [m][n]   64 x 68
    float* mrow = ps + 64 * 68;       // 64
    float* lrow = mrow + 64;          // 64
    float* arow = lrow + 64;          // 64

    const int n0  = blockIdx.x * 64;
    const int b   = blockIdx.y;
    const int tid = threadIdx.x;
    const int tx  = tid & 15;         // S: m = 4*tx+j ; O: d = 8*tx..
    const int ty  = tid >> 4;         // n = 4*ty + i

    // Q tile load (contiguous rows -> [k][n])
#pragma unroll
    for (int r = 0; r < 8; r++) {
        int idx = tid + r * 256;
        int k = idx >> 4, g = idx & 15;
        *(float4*)&qs[k * 68 + 4 * g] =
            *(const float4*)(d_Q + ((size_t)b * DN + k) * HWN + n0 + 4 * g);
    }
    if (tid < 64) { mrow[tid] = -INFINITY; lrow[tid] = 0.f; }

    float o[4][8];
#pragma unroll
    for (int i = 0; i < 4; i++)
#pragma unroll
        for (int j = 0; j < 8; j++) o[i][j] = 0.f;

    for (int m0 = 0; m0 < HWN; m0 += 64) {
        __syncthreads();   // protects ks/vs/ps from previous iteration
        // K tile [k][m]
#pragma unroll
        for (int r = 0; r < 8; r++) {
            int idx = tid + r * 256;
            int k = idx >> 4, g = idx & 15;
            *(float4*)&ks[k * 68 + 4 * g] =
                *(const float4*)(d_Kx + ((size_t)b * DN + k) * HWN + m0 + 4 * g);
        }
        // V tile [m][d]
#pragma unroll
        for (int r = 0; r < 8; r++) {
            int idx = tid + r * 256;
            int m = idx >> 5, g = idx & 31;
            *(float4*)&vs[m * 132 + 4 * g] =
                *(const float4*)(d_G + ((size_t)b * HWN + m0 + m) * DN + 4 * g);
        }
        __syncthreads();

        // ---- S = Q^T K (4x4 per thread) ----
        float s[4][4];
#pragma unroll
        for (int i = 0; i < 4; i++)
#pragma unroll
            for (int j = 0; j < 4; j++) s[i][j] = 0.f;
#pragma unroll 4
        for (int k = 0; k < 128; k++) {
            float4 qv = *(float4*)&qs[k * 68 + 4 * ty];
            float4 kv = *(float4*)&ks[k * 68 + 4 * tx];
            float qr[4] = {qv.x, qv.y, qv.z, qv.w};
            float kr[4] = {kv.x, kv.y, kv.z, kv.w};
#pragma unroll
            for (int i = 0; i < 4; i++)
#pragma unroll
                for (int j = 0; j < 4; j++)
                    s[i][j] += qr[i] * kr[j];
        }
#pragma unroll
        for (int j = 0; j < 4; j++)
            *(float4*)&ps[(4 * tx + j) * 68 + 4 * ty] =
                make_float4(s[0][j], s[1][j], s[2][j], s[3][j]);
        __syncthreads();

        // ---- online softmax: 4 threads per row ----
        {
            int r = tid >> 2, part = tid & 3;
            int mb = part * 16;
            float mx = -INFINITY;
#pragma unroll
            for (int j = 0; j < 16; j++) mx = fmaxf(mx, ps[(mb + j) * 68 + r]);
            mx = fmaxf(mx, __shfl_xor_sync(0xffffffffu, mx, 1));
            mx = fmaxf(mx, __shfl_xor_sync(0xffffffffu, mx, 2));
            float mold = mrow[r];
            float mnew = fmaxf(mold, mx);
            float sum = 0.f;
#pragma unroll
            for (int j = 0; j < 16; j++) {
                float pv = __expf(ps[(mb + j) * 68 + r] - mnew);
                ps[(mb + j) * 68 + r] = pv;
                sum += pv;
            }
            sum += __shfl_xor_sync(0xffffffffu, sum, 1);
            sum += __shfl_xor_sync(0xffffffffu, sum, 2);
            if (part == 0) {
                float alpha = __expf(mold - mnew);
                arow[r] = alpha;
                lrow[r] = lrow[r] * alpha + sum;
                mrow[r] = mnew;
            }
        }
        __syncthreads();

        // ---- O = O*alpha + P @ V ----
        float al[4];
#pragma unroll
        for (int i = 0; i < 4; i++) al[i] = arow[4 * ty + i];
#pragma unroll
        for (int i = 0; i < 4; i++)
#pragma unroll
            for (int j = 0; j < 8; j++) o[i][j] *= al[i];
#pragma unroll 2
        for (int m = 0; m < 64; m++) {
            float4 pv = *(float4*)&ps[m * 68 + 4 * ty];
            float4 v0 = *(float4*)&vs[m * 132 + 8 * tx];
            float4 v1 = *(float4*)&vs[m * 132 + 8 * tx + 4];
            float pr[4] = {pv.x, pv.y, pv.z, pv.w};
            float vr[8] = {v0.x, v0.y, v0.z, v0.w, v1.x, v1.y, v1.z, v1.w};
#pragma unroll
            for (int i = 0; i < 4; i++)
#pragma unroll
                for (int j = 0; j < 8; j++)
                    o[i][j] += pr[i] * vr[j];
        }
    }

    // final normalize + store Y[b][n][i]
#pragma unroll
    for (int i = 0; i < 4; i++) {
        int n = n0 + 4 * ty + i;
        float inv = 1.f / lrow[4 * ty + i];
        float4 v0 = make_float4(o[i][0] * inv, o[i][1] * inv, o[i][2] * inv, o[i][3] * inv);
        float4 v1 = make_float4(o[i][4] * inv, o[i][5] * inv, o[i][6] * inv, o[i][7] * inv);
        *(float4*)(d_Y + ((size_t)b * HWN + n) * DN + 8 * tx)     = v0;
        *(float4*)(d_Y + ((size_t)b * HWN + n) * DN + 8 * tx + 4) = v1;
    }
}

// ============================================================================
// K3: wy[b,c,n] = sum_i W[c,i] * Y[b,n,i] + Wb[c]
// grid = (2, HW/64, B): tile 128 c x 64 n.
// ============================================================================
__global__ void wgemm_kernel(const float* __restrict__ Ww, const float* __restrict__ Wb)
{
    __shared__ float wsI[32][132];   // [it][cc], cc 0..127
    __shared__ float ysI[32][68];    // [it][nn]

    const int c0 = blockIdx.x * 128;
    const int n0 = blockIdx.y * 64;
    const int b  = blockIdx.z;
    const int tid = threadIdx.x;
    const int tx = tid & 15;         // n
    const int ty = tid >> 4;         // c

    float acc[4][8];
#pragma unroll
    for (int i = 0; i < 4; i++)
#pragma unroll
        for (int j = 0; j < 8; j++) acc[i][j] = 0.f;

    for (int i0 = 0; i0 < DN; i0 += 32) {
#pragma unroll
        for (int r = 0; r < 4; r++) {
            int idx = tid + r * 256;          // 0..1023
            int cc = idx >> 3, ig = idx & 7;
            float4 v = *(const float4*)(Ww + (size_t)(c0 + cc) * DN + i0 + 4 * ig);
            wsI[4 * ig + 0][cc] = v.x;
            wsI[4 * ig + 1][cc] = v.y;
            wsI[4 * ig + 2][cc] = v.z;
            wsI[4 * ig + 3][cc] = v.w;
        }
#pragma unroll
        for (int r = 0; r < 2; r++) {
            int idx = tid + r * 256;          // 0..511
            int nn = idx >> 3, ig = idx & 7;
            float4 v = *(const float4*)(d_Y + ((size_t)b * HWN + n0 + nn) * DN + i0 + 4 * ig);
            ysI[4 * ig + 0][nn] = v.x;
            ysI[4 * ig + 1][nn] = v.y;
            ysI[4 * ig + 2][nn] = v.z;
            ysI[4 * ig + 3][nn] = v.w;
        }
        __syncthreads();
#pragma unroll 8
        for (int it = 0; it < 32; it++) {
            float4 yv = *(float4*)&ysI[it][4 * tx];
            float4 w0 = *(float4*)&wsI[it][8 * ty];
            float4 w1 = *(float4*)&wsI[it][8 * ty + 4];
            float yr[4] = {yv.x, yv.y, yv.z, yv.w};
            float wr[8] = {w0.x, w0.y, w0.z, w0.w, w1.x, w1.y, w1.z, w1.w};
#pragma unroll
            for (int i = 0; i < 4; i++)
#pragma unroll
                for (int j = 0; j < 8; j++)
                    acc[i][j] += yr[i] * wr[j];
        }
        __syncthreads();
    }

#pragma unroll
    for (int j = 0; j < 8; j++) {
        int c = c0 + 8 * ty + j;
        float bb = Wb[c];
        float4 v = make_float4(acc[0][j] + bb, acc[1][j] + bb,
                               acc[2][j] + bb, acc[3][j] + bb);
        *(float4*)(d_WY + ((size_t)b * CN + c) * HWN + n0 + 4 * tx) = v;
    }
}

// ============================================================================
// K4: BatchNorm batch statistics per channel (mean, rstd). grid = 256, block = 256
// ============================================================================
__global__ void bnstats_kernel()
{
    const int c = blockIdx.x;
    const int tid = threadIdx.x;
    float s = 0.f, s2 = 0.f;
#pragma unroll
    for (int t = 0; t < BN; t++) {
        const float* row = d_WY + ((size_t)t * CN + c) * HWN;
        for (int n = tid; n < HWN; n += 256) {
            float v = row[n];
            s += v; s2 += v * v;
        }
    }
    __shared__ float sh[256], sh2[256];
    sh[tid] = s; sh2[tid] = s2;
    __syncthreads();
    for (int off = 128; off > 0; off >>= 1) {
        if (tid < off) { sh[tid] += sh[tid + off]; sh2[tid] += sh2[tid + off]; }
        __syncthreads();
    }
    if (tid == 0) {
        const float invN = 1.f / (float)(BN * HWN);
        float mean = sh[0] * invN;
        float var  = sh2[0] * invN - mean * mean;
        d_MEAN[c] = mean;
        d_RSTD[c] = rsqrtf(var + 1e-5f);
    }
}

// ============================================================================
// K5: out = gamma*(wy-mean)*rstd + beta + x   (float4 elementwise)
// ============================================================================
__global__ void finalize_kernel(const float* __restrict__ x,
                                const float* __restrict__ gamma,
                                const float* __restrict__ beta,
                                float* __restrict__ out)
{
    int idx = blockIdx.x * blockDim.x + threadIdx.x;   // float4 index, 1,048,576 total
    int c = (idx >> 10) & 255;                          // 1024 float4 per (b,c) row
    float4 wv = ((const float4*)d_WY)[idx];
    float4 xv = ((const float4*)x)[idx];
    float g  = gamma[c] * d_RSTD[c];
    float m  = d_MEAN[c];
    float bt = beta[c];
    float4 o;
    o.x = (wv.x - m) * g + bt + xv.x;
    o.y = (wv.y - m) * g + bt + xv.y;
    o.z = (wv.z - m) * g + bt + xv.z;
    o.w = (wv.w - m) * g + bt + xv.w;
    ((float4*)out)[idx] = o;
}

// ============================================================================
extern "C" void kernel_launch(void* const* d_in, const int* in_sizes, int n_in,
                              void* d_out, int out_size)
{
    const float* x     = (const float*)d_in[0];
    const float* tw    = (const float*)d_in[1];
    const float* tb    = (const float*)d_in[2];
    const float* pw    = (const float*)d_in[3];
    const float* pb    = (const float*)d_in[4];
    const float* gw    = (const float*)d_in[5];
    const float* gb    = (const float*)d_in[6];
    const float* Ww    = (const float*)d_in[7];
    const float* Wb    = (const float*)d_in[8];
    const float* gamma = (const float*)d_in[9];
    const float* beta  = (const float*)d_in[10];
    float* out = (float*)d_out;

    const int attn_smem = (128 * 68 * 2 + 64 * 132 + 64 * 68 + 192) * (int)sizeof(float);
    cudaFuncSetAttribute(attn_kernel, cudaFuncAttributeMaxDynamicSharedMemorySize, attn_smem);

    dim3 g1(3, HWN / 64, BN);
    proj_kernel<<<g1, 256>>>(x, tw, tb, pw, pb, gw, gb);

    dim3 g2(HWN / 64, BN);
    attn_kernel<<<g2, 256, attn_smem>>>();

    dim3 g3(2, HWN / 64, BN);
    wgemm_kernel<<<g3, 256>>>(Ww, Wb);

    bnstats_kernel<<<CN, 256>>>();

    finalize_kernel<<<(BN * CN * HWN / 4) / 256, 256>>>(x, gamma, beta, out);
}

// round 2
// speedup vs baseline: 1.0008x; 1.0008x over previous
#include <cuda_runtime.h>
#include <math.h>

// Problem constants
#define BN   4
#define CN   256
#define HWN  4096
#define DN   128          // INTER = C/2

// -------------------- scratch (device globals; no allocation) --------------------
__device__ float d_Q [BN * DN * HWN];   // theta, layout [b][i][n]
__device__ float d_Kx[BN * DN * HWN];   // phi,   layout [b][i][n]
__device__ float d_G [BN * HWN * DN];   // g,     layout [b][n][i]
__device__ float d_Y [BN * HWN * DN];   // attn output, layout [b][n][i]
__device__ float d_WY[BN * CN * HWN];   // W*y + b, layout [b][c][n]
__device__ float d_MEAN[CN];
__device__ float d_RSTD[CN];

// ============================================================================
// K1: fused 1x1-conv projections.
//   out[b,i,n] = sum_c x[b,c,n] * w[i,c] + bias[i]
// gridDim = (3 projections, HW/64 tiles, B). Block = 256 threads.
// Tile: 64 n x 128 i. theta/phi stored [i][n]; g stored [n][i] (for V reads).
// ============================================================================
__global__ void proj_kernel(const float* __restrict__ x,
                            const float* __restrict__ tw, const float* __restrict__ tb,
                            const float* __restrict__ pw, const float* __restrict__ pb,
                            const float* __restrict__ gw, const float* __restrict__ gb)
{
    const int p  = blockIdx.x;           // 0=theta, 1=phi, 2=g
    const int n0 = blockIdx.y * 64;
    const int b  = blockIdx.z;
    const float* w    = (p == 0) ? tw : (p == 1) ? pw : gw;
    const float* bias = (p == 0) ? tb : (p == 1) ? pb : gb;

    __shared__ float xs[32][68];    // xs[cc][nn]
    __shared__ float ws[32][132];   // ws[cc][ii], ii in 0..127

    const int tid = threadIdx.x;
    const int tx  = tid & 15;       // n-group: n = n0 + 4*tx + i
    const int ty  = tid >> 4;       // i-group: i = 8*ty + j

    float acc[4][8];
#pragma unroll
    for (int i = 0; i < 4; i++)
#pragma unroll
        for (int j = 0; j < 8; j++) acc[i][j] = 0.f;

    for (int c0 = 0; c0 < CN; c0 += 32) {
        // x tile: 32 c x 64 n (rows contiguous in global)
#pragma unroll
        for (int r = 0; r < 2; r++) {
            int idx = tid + r * 256;            // 0..511
            int cc  = idx >> 4, g = idx & 15;
            float4 v = *(const float4*)(x + ((size_t)b * CN + c0 + cc) * HWN + n0 + 4 * g);
            *(float4*)&xs[cc][4 * g] = v;
        }
        // weight tile transposed: w[ii][c0+cc] -> ws[cc][ii]
#pragma unroll
        for (int r = 0; r < 4; r++) {
            int idx = tid + r * 256;            // 0..1023
            int ii  = idx >> 3, cg = idx & 7;
            float4 v = *(const float4*)(w + (size_t)ii * CN + c0 + 4 * cg);
            ws[4 * cg + 0][ii] = v.x;
            ws[4 * cg + 1][ii] = v.y;
            ws[4 * cg + 2][ii] = v.z;
            ws[4 * cg + 3][ii] = v.w;
        }
        __syncthreads();
#pragma unroll 8
        for (int cc = 0; cc < 32; cc++) {
            float4 xv = *(float4*)&xs[cc][4 * tx];
            float4 w0 = *(float4*)&ws[cc][8 * ty];
            float4 w1 = *(float4*)&ws[cc][8 * ty + 4];
            float xr[4] = {xv.x, xv.y, xv.z, xv.w};
            float wr[8] = {w0.x, w0.y, w0.z, w0.w, w1.x, w1.y, w1.z, w1.w};
#pragma unroll
            for (int i = 0; i < 4; i++)
#pragma unroll
                for (int j = 0; j < 8; j++)
                    acc[i][j] += xr[i] * wr[j];
        }
        __syncthreads();
    }

    if (p < 2) {
        float* out = (p == 0) ? d_Q : d_Kx;     // [b][i][n]
#pragma unroll
        for (int j = 0; j < 8; j++) {
            int ii = 8 * ty + j;
            float bb = bias[ii];
            float4 v = make_float4(acc[0][j] + bb, acc[1][j] + bb,
                                   acc[2][j] + bb, acc[3][j] + bb);
            *(float4*)(out + ((size_t)b * DN + ii) * HWN + n0 + 4 * tx) = v;
        }
    } else {                                    // g -> [b][n][i]
        float b0 = bias[8 * ty + 0], b1 = bias[8 * ty + 1], b2 = bias[8 * ty + 2], b3 = bias[8 * ty + 3];
        float b4 = bias[8 * ty + 4], b5 = bias[8 * ty + 5], b6 = bias[8 * ty + 6], b7 = bias[8 * ty + 7];
#pragma unroll
        for (int i = 0; i < 4; i++) {
            int n = n0 + 4 * tx + i;
            float4 v0 = make_float4(acc[i][0] + b0, acc[i][1] + b1, acc[i][2] + b2, acc[i][3] + b3);
            float4 v1 = make_float4(acc[i][4] + b4, acc[i][5] + b5, acc[i][6] + b6, acc[i][7] + b7);
            *(float4*)(d_G + ((size_t)b * HWN + n) * DN + 8 * ty)     = v0;
            *(float4*)(d_G + ((size_t)b * HWN + n) * DN + 8 * ty + 4) = v1;
        }
    }
}

// ============================================================================
// K2: fused attention (flash style, fp32).
//   f[n,m] = sum_k Q[k,n]*K[k,m];  attn = softmax_m(f);  Y[n,:] = attn @ V
// grid = (HW/64, B), block = 256, dynamic SMEM ~121.6 KB -> 1 CTA/SM.
// ============================================================================
__global__ void attn_kernel()
{
    extern __shared__ float sm[];
    float* qs   = sm;                 // [k][n]  128 x 68
    float* ks   = qs + 128 * 68;      // [k][m]  128 x 68
    float* vs   = ks + 128 * 68;      // [m][d]   64 x 132
    float* ps   = vs + 64 * 132;      // [m][n]   64 x 68
    float* mrow = ps + 64 * 68;       // 64
    float* lrow = mrow + 64;          // 64
    float* arow = lrow + 64;          // 64

    const int n0  = blockIdx.x * 64;
    const int b   = blockIdx.y;
    const int tid = threadIdx.x;
    const int tx  = tid & 15;         // S: m = 4*tx+j ; O: d = 8*tx..
    const int ty  = tid >> 4;         // n = 4*ty + i

    // Q tile load (contiguous rows -> [k][n])
#pragma unroll
    for (int r = 0; r < 8; r++) {
        int idx = tid + r * 256;
        int k = idx >> 4, g = idx & 15;
        *(float4*)&qs[k * 68 + 4 * g] =
            *(const float4*)(d_Q + ((size_t)b * DN + k) * HWN + n0 + 4 * g);
    }
    if (tid < 64) { mrow[tid] = -INFINITY; lrow[tid] = 0.f; }

    float o[4][8];
#pragma unroll
    for (int i = 0; i < 4; i++)
#pragma unroll
        for (int j = 0; j < 8; j++) o[i][j] = 0.f;

    for (int m0 = 0; m0 < HWN; m0 += 64) {
        __syncthreads();   // protects ks/vs/ps from previous iteration
        // K tile [k][m]
#pragma unroll
        for (int r = 0; r < 8; r++) {
            int idx = tid + r * 256;
            int k = idx >> 4, g = idx & 15;
            *(float4*)&ks[k * 68 + 4 * g] =
                *(const float4*)(d_Kx + ((size_t)b * DN + k) * HWN + m0 + 4 * g);
        }
        // V tile [m][d]
#pragma unroll
        for (int r = 0; r < 8; r++) {
            int idx = tid + r * 256;
            int m = idx >> 5, g = idx & 31;
            *(float4*)&vs[m * 132 + 4 * g] =
                *(const float4*)(d_G + ((size_t)b * HWN + m0 + m) * DN + 4 * g);
        }
        __syncthreads();

        // ---- S = Q^T K (4x4 per thread) ----
        float s[4][4];
#pragma unroll
        for (int i = 0; i < 4; i++)
#pragma unroll
            for (int j = 0; j < 4; j++) s[i][j] = 0.f;
#pragma unroll 4
        for (int k = 0; k < 128; k++) {
            float4 qv = *(float4*)&qs[k * 68 + 4 * ty];
            float4 kv = *(float4*)&ks[k * 68 + 4 * tx];
            float qr[4] = {qv.x, qv.y, qv.z, qv.w};
            float kr[4] = {kv.x, kv.y, kv.z, kv.w};
#pragma unroll
            for (int i = 0; i < 4; i++)
#pragma unroll
                for (int j = 0; j < 4; j++)
                    s[i][j] += qr[i] * kr[j];
        }
#pragma unroll
        for (int j = 0; j < 4; j++)
            *(float4*)&ps[(4 * tx + j) * 68 + 4 * ty] =
                make_float4(s[0][j], s[1][j], s[2][j], s[3][j]);
        __syncthreads();

        // ---- online softmax: 4 threads per row ----
        {
            int r = tid >> 2, part = tid & 3;
            int mb = part * 16;
            float mx = -INFINITY;
#pragma unroll
            for (int j = 0; j < 16; j++) mx = fmaxf(mx, ps[(mb + j) * 68 + r]);
            mx = fmaxf(mx, __shfl_xor_sync(0xffffffffu, mx, 1));
            mx = fmaxf(mx, __shfl_xor_sync(0xffffffffu, mx, 2));
            float mold = mrow[r];
            float mnew = fmaxf(mold, mx);
            float sum = 0.f;
#pragma unroll
            for (int j = 0; j < 16; j++) {
                float pv = __expf(ps[(mb + j) * 68 + r] - mnew);
                ps[(mb + j) * 68 + r] = pv;
                sum += pv;
            }
            sum += __shfl_xor_sync(0xffffffffu, sum, 1);
            sum += __shfl_xor_sync(0xffffffffu, sum, 2);
            if (part == 0) {
                float alpha = __expf(mold - mnew);
                arow[r] = alpha;
                lrow[r] = lrow[r] * alpha + sum;
                mrow[r] = mnew;
            }
        }
        __syncthreads();

        // ---- O = O*alpha + P @ V ----
        float al[4];
#pragma unroll
        for (int i = 0; i < 4; i++) al[i] = arow[4 * ty + i];
#pragma unroll
        for (int i = 0; i < 4; i++)
#pragma unroll
            for (int j = 0; j < 8; j++) o[i][j] *= al[i];
#pragma unroll 2
        for (int m = 0; m < 64; m++) {
            float4 pv = *(float4*)&ps[m * 68 + 4 * ty];
            float4 v0 = *(float4*)&vs[m * 132 + 8 * tx];
            float4 v1 = *(float4*)&vs[m * 132 + 8 * tx + 4];
            float pr[4] = {pv.x, pv.y, pv.z, pv.w};
            float vr[8] = {v0.x, v0.y, v0.z, v0.w, v1.x, v1.y, v1.z, v1.w};
#pragma unroll
            for (int i = 0; i < 4; i++)
#pragma unroll
                for (int j = 0; j < 8; j++)
                    o[i][j] += pr[i] * vr[j];
        }
    }

    // final normalize + store Y[b][n][i]
#pragma unroll
    for (int i = 0; i < 4; i++) {
        int n = n0 + 4 * ty + i;
        float inv = 1.f / lrow[4 * ty + i];
        float4 v0 = make_float4(o[i][0] * inv, o[i][1] * inv, o[i][2] * inv, o[i][3] * inv);
        float4 v1 = make_float4(o[i][4] * inv, o[i][5] * inv, o[i][6] * inv, o[i][7] * inv);
        *(float4*)(d_Y + ((size_t)b * HWN + n) * DN + 8 * tx)     = v0;
        *(float4*)(d_Y + ((size_t)b * HWN + n) * DN + 8 * tx + 4) = v1;
    }
}

// ============================================================================
// K3: wy[b,c,n] = sum_i W[c,i] * Y[b,n,i] + Wb[c]
// grid = (2, HW/64, B): tile 128 c x 64 n.
// ============================================================================
__global__ void wgemm_kernel(const float* __restrict__ Ww, const float* __restrict__ Wb)
{
    __shared__ float wsI[32][132];   // [it][cc], cc 0..127
    __shared__ float ysI[32][68];    // [it][nn]

    const int c0 = blockIdx.x * 128;
    const int n0 = blockIdx.y * 64;
    const int b  = blockIdx.z;
    const int tid = threadIdx.x;
    const int tx = tid & 15;         // n
    const int ty = tid >> 4;         // c

    float acc[4][8];
#pragma unroll
    for (int i = 0; i < 4; i++)
#pragma unroll
        for (int j = 0; j < 8; j++) acc[i][j] = 0.f;

    for (int i0 = 0; i0 < DN; i0 += 32) {
#pragma unroll
        for (int r = 0; r < 4; r++) {
            int idx = tid + r * 256;          // 0..1023
            int cc = idx >> 3, ig = idx & 7;
            float4 v = *(const float4*)(Ww + (size_t)(c0 + cc) * DN + i0 + 4 * ig);
            wsI[4 * ig + 0][cc] = v.x;
            wsI[4 * ig + 1][cc] = v.y;
            wsI[4 * ig + 2][cc] = v.z;
            wsI[4 * ig + 3][cc] = v.w;
        }
#pragma unroll
        for (int r = 0; r < 2; r++) {
            int idx = tid + r * 256;          // 0..511
            int nn = idx >> 3, ig = idx & 7;
            float4 v = *(const float4*)(d_Y + ((size_t)b * HWN + n0 + nn) * DN + i0 + 4 * ig);
            ysI[4 * ig + 0][nn] = v.x;
            ysI[4 * ig + 1][nn] = v.y;
            ysI[4 * ig + 2][nn] = v.z;
            ysI[4 * ig + 3][nn] = v.w;
        }
        __syncthreads();
#pragma unroll 8
        for (int it = 0; it < 32; it++) {
            float4 yv = *(float4*)&ysI[it][4 * tx];
            float4 w0 = *(float4*)&wsI[it][8 * ty];
            float4 w1 = *(float4*)&wsI[it][8 * ty + 4];
            float yr[4] = {yv.x, yv.y, yv.z, yv.w};
            float wr[8] = {w0.x, w0.y, w0.z, w0.w, w1.x, w1.y, w1.z, w1.w};
#pragma unroll
            for (int i = 0; i < 4; i++)
#pragma unroll
                for (int j = 0; j < 8; j++)
                    acc[i][j] += yr[i] * wr[j];
        }
        __syncthreads();
    }

#pragma unroll
    for (int j = 0; j < 8; j++) {
        int c = c0 + 8 * ty + j;
        float bb = Wb[c];
        float4 v = make_float4(acc[0][j] + bb, acc[1][j] + bb,
                               acc[2][j] + bb, acc[3][j] + bb);
        *(float4*)(d_WY + ((size_t)b * CN + c) * HWN + n0 + 4 * tx) = v;
    }
}

// ============================================================================
// K4: BatchNorm batch statistics per channel (mean, rstd). grid = 256, block = 256
// ============================================================================
__global__ void bnstats_kernel()
{
    const int c = blockIdx.x;
    const int tid = threadIdx.x;
    float s = 0.f, s2 = 0.f;
#pragma unroll
    for (int t = 0; t < BN; t++) {
        const float* row = d_WY + ((size_t)t * CN + c) * HWN;
        for (int n = tid; n < HWN; n += 256) {
            float v = row[n];
            s += v; s2 += v * v;
        }
    }
    __shared__ float sh[256], sh2[256];
    sh[tid] = s; sh2[tid] = s2;
    __syncthreads();
    for (int off = 128; off > 0; off >>= 1) {
        if (tid < off) { sh[tid] += sh[tid + off]; sh2[tid] += sh2[tid + off]; }
        __syncthreads();
    }
    if (tid == 0) {
        const float invN = 1.f / (float)(BN * HWN);
        float mean = sh[0] * invN;
        float var  = sh2[0] * invN - mean * mean;
        d_MEAN[c] = mean;
        d_RSTD[c] = rsqrtf(var + 1e-5f);
    }
}

// ============================================================================
// K5: out = gamma*(wy-mean)*rstd + beta + x   (float4 elementwise)
// ============================================================================
__global__ void finalize_kernel(const float* __restrict__ x,
                                const float* __restrict__ gamma,
                                const float* __restrict__ beta,
                                float* __restrict__ out)
{
    int idx = blockIdx.x * blockDim.x + threadIdx.x;   // float4 index, 1,048,576 total
    int c = (idx >> 10) & 255;                          // 1024 float4 per (b,c) row
    float4 wv = ((const float4*)d_WY)[idx];
    float4 xv = ((const float4*)x)[idx];
    float g  = gamma[c] * d_RSTD[c];
    float m  = d_MEAN[c];
    float bt = beta[c];
    float4 o;
    o.x = (wv.x - m) * g + bt + xv.x;
    o.y = (wv.y - m) * g + bt + xv.y;
    o.z = (wv.z - m) * g + bt + xv.z;
    o.w = (wv.w - m) * g + bt + xv.w;
    ((float4*)out)[idx] = o;
}

// ============================================================================
extern "C" void kernel_launch(void* const* d_in, const int* in_sizes, int n_in,
                              void* d_out, int out_size)
{
    const float* x     = (const float*)d_in[0];
    const float* tw    = (const float*)d_in[1];
    const float* tb    = (const float*)d_in[2];
    const float* pw    = (const float*)d_in[3];
    const float* pb    = (const float*)d_in[4];
    const float* gw    = (const float*)d_in[5];
    const float* gb    = (const float*)d_in[6];
    const float* Ww    = (const float*)d_in[7];
    const float* Wb    = (const float*)d_in[8];
    const float* gamma = (const float*)d_in[9];
    const float* beta  = (const float*)d_in[10];
    float* out = (float*)d_out;

    const int attn_smem = (128 * 68 * 2 + 64 * 132 + 64 * 68 + 192) * (int)sizeof(float);
    cudaFuncSetAttribute(attn_kernel, cudaFuncAttributeMaxDynamicSharedMemorySize, attn_smem);

    dim3 g1(3, HWN / 64, BN);
    proj_kernel<<<g1, 256>>>(x, tw, tb, pw, pb, gw, gb);

    dim3 g2(HWN / 64, BN);
    attn_kernel<<<g2, 256, attn_smem>>>();

    dim3 g3(2, HWN / 64, BN);
    wgemm_kernel<<<g3, 256>>>(Ww, Wb);

    bnstats_kernel<<<CN, 256>>>();

    finalize_kernel<<<(BN * CN * HWN / 4) / 256, 256>>>(x, gamma, beta, out);
}

// round 4
// speedup vs baseline: 3.6337x; 3.6309x over previous
#include <cuda_runtime.h>
#include <cuda_bf16.h>
#include <math.h>
#include <stdint.h>

#define BN   4
#define CN   256
#define HWN  4096
#define DN   128
#define TM   128            // queries per CTA
#define TN   64             // keys per tile

// smem stage layout (bytes): padded rows for conflict-free B-frag LDS
#define K_ROW   272         // 256B data + 16B pad  (stride ≡ 4 banks)
#define V_ROW   144         // 128B data + 16B pad
#define KH_OFF  0
#define KL_OFF  (64 * K_ROW)                 // 17408
#define VH_OFF  (2 * 64 * K_ROW)             // 34816
#define VL_OFF  (2 * 64 * K_ROW + 128 * V_ROW)
#define STG_SZ  (2 * 64 * K_ROW + 2 * 128 * V_ROW)   // 71680
#define ATTN_SMEM (2 * STG_SZ)                        // 143360

// -------------------- scratch --------------------
__device__ __align__(128) __nv_bfloat16 gQh[BN * HWN * DN];  // theta hi [b][n][k]
__device__ __align__(128) __nv_bfloat16 gQl[BN * HWN * DN];
__device__ __align__(128) __nv_bfloat16 gKh[BN * HWN * DN];  // phi hi   [b][m][k]
__device__ __align__(128) __nv_bfloat16 gKl[BN * HWN * DN];
__device__ __align__(128) __nv_bfloat16 gVh[BN * DN * HWN];  // g hi     [b][d][m]
__device__ __align__(128) __nv_bfloat16 gVl[BN * DN * HWN];
__device__ __align__(128) float d_Y [BN * HWN * DN];         // [b][n][i]
__device__ __align__(128) float d_WY[BN * CN * HWN];         // [b][c][n]
__device__ float d_MEAN[CN];
__device__ float d_RSTD[CN];

// ======================= helpers =======================
__device__ __forceinline__ uint32_t smem_u32(const void* p) {
    uint32_t a;
    asm("{ .reg .u64 t; cvta.to.shared.u64 t, %1; cvt.u32.u64 %0, t; }" : "=r"(a) : "l"(p));
    return a;
}
__device__ __forceinline__ void cp16(uint32_t dst, const void* src) {
    asm volatile("cp.async.cg.shared.global [%0], [%1], 16;" :: "r"(dst), "l"(src));
}
#define CP_COMMIT() asm volatile("cp.async.commit_group;" ::: "memory")
#define CP_WAIT0()  asm volatile("cp.async.wait_group 0;" ::: "memory")
#define CP_WAIT1()  asm volatile("cp.async.wait_group 1;" ::: "memory")

__device__ __forceinline__ void mma_bf16(float& c0, float& c1, float& c2, float& c3,
                                         uint32_t a0, uint32_t a1, uint32_t a2, uint32_t a3,
                                         uint32_t b0, uint32_t b1) {
    asm volatile("mma.sync.aligned.m16n8k16.row.col.f32.bf16.bf16.f32 "
                 "{%0,%1,%2,%3}, {%4,%5,%6,%7}, {%8,%9}, {%0,%1,%2,%3};"
                 : "+f"(c0), "+f"(c1), "+f"(c2), "+f"(c3)
                 : "r"(a0), "r"(a1), "r"(a2), "r"(a3), "r"(b0), "r"(b1));
}
__device__ __forceinline__ uint32_t lds32(uint32_t addr) {
    uint32_t v;
    asm volatile("ld.shared.b32 %0, [%1];" : "=r"(v) : "r"(addr));
    return v;
}
__device__ __forceinline__ void split2(float v0, float v1, uint32_t& hi, uint32_t& lo) {
    __nv_bfloat16 h0 = __float2bfloat16(v0);
    __nv_bfloat16 h1 = __float2bfloat16(v1);
    float r0 = v0 - __bfloat162float(h0);
    float r1 = v1 - __bfloat162float(h1);
    __nv_bfloat162 hh; hh.x = h0; hh.y = h1;
    __nv_bfloat162 ll; ll.x = __float2bfloat16(r0); ll.y = __float2bfloat16(r1);
    hi = *(uint32_t*)&hh;
    lo = *(uint32_t*)&ll;
}

// ============================================================================
// K1: fused 1x1-conv projections, bf16 hi/lo outputs in MMA layouts.
// ============================================================================
__global__ void proj_kernel(const float* __restrict__ x,
                            const float* __restrict__ tw, const float* __restrict__ tb,
                            const float* __restrict__ pw, const float* __restrict__ pb,
                            const float* __restrict__ gw, const float* __restrict__ gb)
{
    const int p  = blockIdx.x;
    const int n0 = blockIdx.y * 64;
    const int b  = blockIdx.z;
    const float* w    = (p == 0) ? tw : (p == 1) ? pw : gw;
    const float* bias = (p == 0) ? tb : (p == 1) ? pb : gb;

    __shared__ float xs[32][68];
    __shared__ float ws[32][132];

    const int tid = threadIdx.x;
    const int tx  = tid & 15;
    const int ty  = tid >> 4;

    float acc[4][8];
#pragma unroll
    for (int i = 0; i < 4; i++)
#pragma unroll
        for (int j = 0; j < 8; j++) acc[i][j] = 0.f;

    for (int c0 = 0; c0 < CN; c0 += 32) {
#pragma unroll
        for (int r = 0; r < 2; r++) {
            int idx = tid + r * 256;
            int cc  = idx >> 4, g = idx & 15;
            *(float4*)&xs[cc][4 * g] =
                *(const float4*)(x + ((size_t)b * CN + c0 + cc) * HWN + n0 + 4 * g);
        }
#pragma unroll
        for (int r = 0; r < 4; r++) {
            int idx = tid + r * 256;
            int ii  = idx >> 3, cg = idx & 7;
            float4 v = *(const float4*)(w + (size_t)ii * CN + c0 + 4 * cg);
            ws[4 * cg + 0][ii] = v.x;
            ws[4 * cg + 1][ii] = v.y;
            ws[4 * cg + 2][ii] = v.z;
            ws[4 * cg + 3][ii] = v.w;
        }
        __syncthreads();
#pragma unroll 8
        for (int cc = 0; cc < 32; cc++) {
            float4 xv = *(float4*)&xs[cc][4 * tx];
            float4 w0 = *(float4*)&ws[cc][8 * ty];
            float4 w1 = *(float4*)&ws[cc][8 * ty + 4];
            float xr[4] = {xv.x, xv.y, xv.z, xv.w};
            float wr[8] = {w0.x, w0.y, w0.z, w0.w, w1.x, w1.y, w1.z, w1.w};
#pragma unroll
            for (int i = 0; i < 4; i++)
#pragma unroll
                for (int j = 0; j < 8; j++)
                    acc[i][j] += xr[i] * wr[j];
        }
        __syncthreads();
    }

    float bj[8];
#pragma unroll
    for (int j = 0; j < 8; j++) bj[j] = bias[8 * ty + j];

    if (p < 2) {                                  // theta/phi -> [b][n][k]
        __nv_bfloat16* oh = (p == 0) ? gQh : gKh;
        __nv_bfloat16* ol = (p == 0) ? gQl : gKl;
#pragma unroll
        for (int i = 0; i < 4; i++) {
            int n = n0 + 4 * tx + i;
            size_t base = ((size_t)b * HWN + n) * DN + 8 * ty;
#pragma unroll
            for (int e = 0; e < 4; e++) {
                uint32_t hi, lo;
                split2(acc[i][2 * e] + bj[2 * e], acc[i][2 * e + 1] + bj[2 * e + 1], hi, lo);
                *(uint32_t*)(oh + base + 2 * e) = hi;
                *(uint32_t*)(ol + base + 2 * e) = lo;
            }
        }
    } else {                                      // g -> [b][d][m]
#pragma unroll
        for (int j = 0; j < 8; j++) {
            int dd = 8 * ty + j;
            size_t base = ((size_t)b * DN + dd) * HWN + n0 + 4 * tx;
            uint32_t h0, l0, h1, l1;
            split2(acc[0][j] + bj[j], acc[1][j] + bj[j], h0, l0);
            split2(acc[2][j] + bj[j], acc[3][j] + bj[j], h1, l1);
            *(uint32_t*)(gVh + base)     = h0;
            *(uint32_t*)(gVh + base + 2) = h1;
            *(uint32_t*)(gVl + base)     = l0;
            *(uint32_t*)(gVl + base + 2) = l1;
        }
    }
}

// ============================================================================
// K2: mma.sync bf16 split-2 flash attention. grid (32, 4), block 256 (8 warps).
//   Each warp owns 16 query rows. Keys swept in 64-wide tiles, K/V double-
//   buffered in SMEM via cp.async. Unnormalized softmax, one normalize at end.
// ============================================================================
__device__ __forceinline__ void load_kv_tile(uint32_t stg, int b, int m0, int tid) {
#pragma unroll
    for (int r = 0; r < 4; r++) {           // K: 64 rows x 256B (16 chunks)
        int ch = tid + (r << 8);            // 0..1023
        int rw = ch >> 4;
        int kc = ch & 15;
        uint32_t dst = stg + rw * K_ROW + (kc << 4);
        size_t gi = (((size_t)b * HWN + m0 + rw) << 7) + (kc << 3);
        cp16(dst + KH_OFF, gKh + gi);
        cp16(dst + KL_OFF, gKl + gi);
    }
#pragma unroll
    for (int r = 0; r < 4; r++) {           // V: 128 rows(d) x 128B (8 chunks)
        int ch = tid + (r << 8);
        int rw = ch >> 3;
        int mc = ch & 7;
        uint32_t dst = stg + rw * V_ROW + (mc << 4);
        size_t gi = (((size_t)b * DN + rw) << 12) + m0 + (mc << 3);
        cp16(dst + VH_OFF, gVh + gi);
        cp16(dst + VL_OFF, gVl + gi);
    }
}

__global__ void __launch_bounds__(256, 1) attn_mma_kernel()
{
    extern __shared__ char smem[];
    const uint32_t smb = smem_u32(smem);

    const int tid  = threadIdx.x;
    const int wrp  = tid >> 5;
    const int lane = tid & 31;
    const int qrow = lane >> 2;            // 0..7 within fragment
    const int qcol = lane & 3;             // quad column
    const int n0   = blockIdx.x * TM;
    const int b    = blockIdx.y;
    const int row0 = 16 * wrp + qrow;      // local query row (of 128)

    // ---- Q fragments in registers (8 k-steps, hi+lo) ----
    uint32_t qh[8][4], ql[8][4];
    {
        const size_t rbase = ((size_t)b * HWN + n0 + row0) * DN;
#pragma unroll
        for (int ks = 0; ks < 8; ks++) {
            int k0 = 16 * ks + 2 * qcol;
            qh[ks][0] = *(const uint32_t*)(gQh + rbase + k0);
            qh[ks][1] = *(const uint32_t*)(gQh + rbase + 8 * DN + k0);
            qh[ks][2] = *(const uint32_t*)(gQh + rbase + k0 + 8);
            qh[ks][3] = *(const uint32_t*)(gQh + rbase + 8 * DN + k0 + 8);
            ql[ks][0] = *(const uint32_t*)(gQl + rbase + k0);
            ql[ks][1] = *(const uint32_t*)(gQl + rbase + 8 * DN + k0);
            ql[ks][2] = *(const uint32_t*)(gQl + rbase + k0 + 8);
            ql[ks][3] = *(const uint32_t*)(gQl + rbase + 8 * DN + k0 + 8);
        }
    }

    // ---- O accumulators: 16 d-tiles x 4 ----
    float o[16][4];
#pragma unroll
    for (int i = 0; i < 16; i++)
#pragma unroll
        for (int j = 0; j < 4; j++) o[i][j] = 0.f;

    float rs0 = 0.f, rs1 = 0.f;            // unnormalized row sums (rows row0, row0+8)

    // prologue: stage 0
    load_kv_tile(smb, b, 0, tid);
    CP_COMMIT();

    for (int t = 0; t < 64; t++) {
        const uint32_t stg = smb + (uint32_t)(t & 1) * STG_SZ;
        __syncthreads();                   // all warps done reading the stage we overwrite
        if (t + 1 < 64) {
            load_kv_tile(smb + (uint32_t)((t + 1) & 1) * STG_SZ, b, (t + 1) * TN, tid);
            CP_COMMIT();
            CP_WAIT1();
        } else {
            CP_WAIT0();
        }
        __syncthreads();                   // stage t fully resident for all warps

        // ---- S = Q K^T (split-2: hh + hl + lh), 8 key-tiles of 8 ----
        uint32_t ph[8][2], pl[8][2];
#pragma unroll
        for (int nt = 0; nt < 8; nt++) {
            float c0 = 0.f, c1 = 0.f, c2 = 0.f, c3 = 0.f;
            const uint32_t krow = stg + (uint32_t)(8 * nt + qrow) * K_ROW + (uint32_t)(4 * qcol);
#pragma unroll
            for (int ks = 0; ks < 8; ks++) {
                uint32_t bh0 = lds32(krow + KH_OFF + 32 * ks);
                uint32_t bh1 = lds32(krow + KH_OFF + 32 * ks + 16);
                uint32_t bl0 = lds32(krow + KL_OFF + 32 * ks);
                uint32_t bl1 = lds32(krow + KL_OFF + 32 * ks + 16);
                mma_bf16(c0, c1, c2, c3, qh[ks][0], qh[ks][1], qh[ks][2], qh[ks][3], bh0, bh1);
                mma_bf16(c0, c1, c2, c3, qh[ks][0], qh[ks][1], qh[ks][2], qh[ks][3], bl0, bl1);
                mma_bf16(c0, c1, c2, c3, ql[ks][0], ql[ks][1], ql[ks][2], ql[ks][3], bh0, bh1);
            }
            // exp (unnormalized) + split to bf16 hi/lo P fragments
            float e0 = __expf(c0), e1 = __expf(c1);
            float e2 = __expf(c2), e3 = __expf(c3);
            rs0 += e0 + e1;
            rs1 += e2 + e3;
            split2(e0, e1, ph[nt][0], pl[nt][0]);
            split2(e2, e3, ph[nt][1], pl[nt][1]);
        }

        // ---- O += P V (split-2), 16 d-tiles x 4 m-steps ----
#pragma unroll
        for (int ks = 0; ks < 4; ks++) {
            uint32_t ah0 = ph[2 * ks][0], ah1 = ph[2 * ks][1];
            uint32_t ah2 = ph[2 * ks + 1][0], ah3 = ph[2 * ks + 1][1];
            uint32_t al0 = pl[2 * ks][0], al1 = pl[2 * ks][1];
            uint32_t al2 = pl[2 * ks + 1][0], al3 = pl[2 * ks + 1][1];
            const uint32_t vcol = stg + (uint32_t)(32 * ks + 4 * qcol);
#pragma unroll
            for (int nt = 0; nt < 16; nt++) {
                const uint32_t vrow = vcol + (uint32_t)(8 * nt + qrow) * V_ROW;
                uint32_t bh0 = lds32(vrow + VH_OFF);
                uint32_t bh1 = lds32(vrow + VH_OFF + 16);
                uint32_t bl0 = lds32(vrow + VL_OFF);
                uint32_t bl1 = lds32(vrow + VL_OFF + 16);
                mma_bf16(o[nt][0], o[nt][1], o[nt][2], o[nt][3], ah0, ah1, ah2, ah3, bh0, bh1);
                mma_bf16(o[nt][0], o[nt][1], o[nt][2], o[nt][3], ah0, ah1, ah2, ah3, bl0, bl1);
                mma_bf16(o[nt][0], o[nt][1], o[nt][2], o[nt][3], al0, al1, al2, al3, bh0, bh1);
            }
        }
    }

    // ---- normalize + store ----
    rs0 += __shfl_xor_sync(0xffffffffu, rs0, 1);
    rs0 += __shfl_xor_sync(0xffffffffu, rs0, 2);
    rs1 += __shfl_xor_sync(0xffffffffu, rs1, 1);
    rs1 += __shfl_xor_sync(0xffffffffu, rs1, 2);
    float inv0 = 1.f / rs0;
    float inv1 = 1.f / rs1;

    float* y0 = d_Y + ((size_t)b * HWN + n0 + row0) * DN + 2 * qcol;
    float* y1 = y0 + 8 * DN;
#pragma unroll
    for (int nt = 0; nt < 16; nt++) {
        *(float2*)(y0 + 8 * nt) = make_float2(o[nt][0] * inv0, o[nt][1] * inv0);
        *(float2*)(y1 + 8 * nt) = make_float2(o[nt][2] * inv1, o[nt][3] * inv1);
    }
}

// ============================================================================
// K3: wy[b,c,n] = sum_i W[c,i] * Y[b,n,i] + Wb[c]
// ============================================================================
__global__ void wgemm_kernel(const float* __restrict__ Ww, const float* __restrict__ Wb)
{
    __shared__ float wsI[32][132];
    __shared__ float ysI[32][68];

    const int c0 = blockIdx.x * 128;
    const int n0 = blockIdx.y * 64;
    const int b  = blockIdx.z;
    const int tid = threadIdx.x;
    const int tx = tid & 15;
    const int ty = tid >> 4;

    float acc[4][8];
#pragma unroll
    for (int i = 0; i < 4; i++)
#pragma unroll
        for (int j = 0; j < 8; j++) acc[i][j] = 0.f;

    for (int i0 = 0; i0 < DN; i0 += 32) {
#pragma unroll
        for (int r = 0; r < 4; r++) {
            int idx = tid + r * 256;
            int cc = idx >> 3, ig = idx & 7;
            float4 v = *(const float4*)(Ww + (size_t)(c0 + cc) * DN + i0 + 4 * ig);
            wsI[4 * ig + 0][cc] = v.x;
            wsI[4 * ig + 1][cc] = v.y;
            wsI[4 * ig + 2][cc] = v.z;
            wsI[4 * ig + 3][cc] = v.w;
        }
#pragma unroll
        for (int r = 0; r < 2; r++) {
            int idx = tid + r * 256;
            int nn = idx >> 3, ig = idx & 7;
            float4 v = *(const float4*)(d_Y + ((size_t)b * HWN + n0 + nn) * DN + i0 + 4 * ig);
            ysI[4 * ig + 0][nn] = v.x;
            ysI[4 * ig + 1][nn] = v.y;
            ysI[4 * ig + 2][nn] = v.z;
            ysI[4 * ig + 3][nn] = v.w;
        }
        __syncthreads();
#pragma unroll 8
        for (int it = 0; it < 32; it++) {
            float4 yv = *(float4*)&ysI[it][4 * tx];
            float4 w0 = *(float4*)&wsI[it][8 * ty];
            float4 w1 = *(float4*)&wsI[it][8 * ty + 4];
            float yr[4] = {yv.x, yv.y, yv.z, yv.w};
            float wr[8] = {w0.x, w0.y, w0.z, w0.w, w1.x, w1.y, w1.z, w1.w};
#pragma unroll
            for (int i = 0; i < 4; i++)
#pragma unroll
                for (int j = 0; j < 8; j++)
                    acc[i][j] += yr[i] * wr[j];
        }
        __syncthreads();
    }

#pragma unroll
    for (int j = 0; j < 8; j++) {
        int c = c0 + 8 * ty + j;
        float bb = Wb[c];
        float4 v = make_float4(acc[0][j] + bb, acc[1][j] + bb,
                               acc[2][j] + bb, acc[3][j] + bb);
        *(float4*)(d_WY + ((size_t)b * CN + c) * HWN + n0 + 4 * tx) = v;
    }
}

// ============================================================================
// K4: BN stats
// ============================================================================
__global__ void bnstats_kernel()
{
    const int c = blockIdx.x;
    const int tid = threadIdx.x;
    float s = 0.f, s2 = 0.f;
#pragma unroll
    for (int t = 0; t < BN; t++) {
        const float* row = d_WY + ((size_t)t * CN + c) * HWN;
        for (int n = tid; n < HWN; n += 256) {
            float v = row[n];
            s += v; s2 += v * v;
        }
    }
    __shared__ float sh[256], sh2[256];
    sh[tid] = s; sh2[tid] = s2;
    __syncthreads();
    for (int off = 128; off > 0; off >>= 1) {
        if (tid < off) { sh[tid] += sh[tid + off]; sh2[tid] += sh2[tid + off]; }
        __syncthreads();
    }
    if (tid == 0) {
        const float invN = 1.f / (float)(BN * HWN);
        float mean = sh[0] * invN;
        float var  = sh2[0] * invN - mean * mean;
        d_MEAN[c] = mean;
        d_RSTD[c] = rsqrtf(var + 1e-5f);
    }
}

// ============================================================================
// K5: finalize
// ============================================================================
__global__ void finalize_kernel(const float* __restrict__ x,
                                const float* __restrict__ gamma,
                                const float* __restrict__ beta,
                                float* __restrict__ out)
{
    int idx = blockIdx.x * blockDim.x + threadIdx.x;
    int c = (idx >> 10) & 255;
    float4 wv = ((const float4*)d_WY)[idx];
    float4 xv = ((const float4*)x)[idx];
    float g  = gamma[c] * d_RSTD[c];
    float m  = d_MEAN[c];
    float bt = beta[c];
    float4 o;
    o.x = (wv.x - m) * g + bt + xv.x;
    o.y = (wv.y - m) * g + bt + xv.y;
    o.z = (wv.z - m) * g + bt + xv.z;
    o.w = (wv.w - m) * g + bt + xv.w;
    ((float4*)out)[idx] = o;
}

// ============================================================================
extern "C" void kernel_launch(void* const* d_in, const int* in_sizes, int n_in,
                              void* d_out, int out_size)
{
    const float* x     = (const float*)d_in[0];
    const float* tw    = (const float*)d_in[1];
    const float* tb    = (const float*)d_in[2];
    const float* pw    = (const float*)d_in[3];
    const float* pb    = (const float*)d_in[4];
    const float* gw    = (const float*)d_in[5];
    const float* gb    = (const float*)d_in[6];
    const float* Ww    = (const float*)d_in[7];
    const float* Wb    = (const float*)d_in[8];
    const float* gamma = (const float*)d_in[9];
    const float* beta  = (const float*)d_in[10];
    float* out = (float*)d_out;

    cudaFuncSetAttribute(attn_mma_kernel, cudaFuncAttributeMaxDynamicSharedMemorySize, ATTN_SMEM);

    dim3 g1(3, HWN / 64, BN);
    proj_kernel<<<g1, 256>>>(x, tw, tb, pw, pb, gw, gb);

    dim3 g2(HWN / TM, BN);
    attn_mma_kernel<<<g2, 256, ATTN_SMEM>>>();

    dim3 g3(2, HWN / 64, BN);
    wgemm_kernel<<<g3, 256>>>(Ww, Wb);

    bnstats_kernel<<<CN, 256>>>();

    finalize_kernel<<<(BN * CN * HWN / 4) / 256, 256>>>(x, gamma, beta, out);
}

// round 6
// speedup vs baseline: 3.6939x; 1.0166x over previous
#include <cuda_runtime.h>
#include <cuda_bf16.h>
#include <math.h>
#include <stdint.h>

#define BN   4
#define CN   256
#define HWN  4096
#define DN   128
#define TM   128            // queries per CTA (attention)
#define TN   64             // keys per tile

// attention smem stage layout (bytes)
#define K_ROW   272
#define V_ROW   144
#define KH_OFF  0
#define KL_OFF  (64 * K_ROW)
#define VH_OFF  (2 * 64 * K_ROW)
#define VL_OFF  (2 * 64 * K_ROW + 128 * V_ROW)
#define STG_SZ  (2 * 64 * K_ROW + 2 * 128 * V_ROW)   // 71680
#define ATTN_SMEM (2 * STG_SZ)                        // 143360

// proj smem layout (bytes): xs fp32 [64][66], wsh/wsl bf16 [128][68]
#define PX_OFF   0
#define PWH_OFF  16896
#define PWL_OFF  34304
#define PRJ_SMEM 51712

// -------------------- scratch --------------------
__device__ __align__(128) __nv_bfloat16 gQh[BN * HWN * DN];  // theta hi [b][n][k]
__device__ __align__(128) __nv_bfloat16 gQl[BN * HWN * DN];
__device__ __align__(128) __nv_bfloat16 gKh[BN * HWN * DN];  // phi hi   [b][m][k]
__device__ __align__(128) __nv_bfloat16 gKl[BN * HWN * DN];
__device__ __align__(128) __nv_bfloat16 gVh[BN * DN * HWN];  // g hi     [b][d][m]
__device__ __align__(128) __nv_bfloat16 gVl[BN * DN * HWN];
__device__ __align__(128) float d_Y [BN * HWN * DN];         // [b][n][i]
__device__ __align__(128) float d_WY[BN * CN * HWN];         // [b][c][n]
__device__ float gPS[CN * 256];     // per-CTA partial sums   [c][part]
__device__ float gPQ[CN * 256];     // per-CTA partial sq-sums
__device__ float d_MEAN[CN];
__device__ float d_RSTD[CN];

// ======================= helpers =======================
__device__ __forceinline__ uint32_t smem_u32(const void* p) {
    uint32_t a;
    asm("{ .reg .u64 t; cvta.to.shared.u64 t, %1; cvt.u32.u64 %0, t; }" : "=r"(a) : "l"(p));
    return a;
}
__device__ __forceinline__ void cp16(uint32_t dst, const void* src) {
    asm volatile("cp.async.cg.shared.global [%0], [%1], 16;" :: "r"(dst), "l"(src));
}
#define CP_COMMIT() asm volatile("cp.async.commit_group;" ::: "memory")
#define CP_WAIT0()  asm volatile("cp.async.wait_group 0;" ::: "memory")
#define CP_WAIT1()  asm volatile("cp.async.wait_group 1;" ::: "memory")

__device__ __forceinline__ void mma_bf16(float& c0, float& c1, float& c2, float& c3,
                                         uint32_t a0, uint32_t a1, uint32_t a2, uint32_t a3,
                                         uint32_t b0, uint32_t b1) {
    asm volatile("mma.sync.aligned.m16n8k16.row.col.f32.bf16.bf16.f32 "
                 "{%0,%1,%2,%3}, {%4,%5,%6,%7}, {%8,%9}, {%0,%1,%2,%3};"
                 : "+f"(c0), "+f"(c1), "+f"(c2), "+f"(c3)
                 : "r"(a0), "r"(a1), "r"(a2), "r"(a3), "r"(b0), "r"(b1));
}
__device__ __forceinline__ uint32_t lds32(uint32_t addr) {
    uint32_t v;
    asm volatile("ld.shared.b32 %0, [%1];" : "=r"(v) : "r"(addr));
    return v;
}
__device__ __forceinline__ void split2(float v0, float v1, uint32_t& hi, uint32_t& lo) {
    __nv_bfloat16 h0 = __float2bfloat16(v0);
    __nv_bfloat16 h1 = __float2bfloat16(v1);
    float r0 = v0 - __bfloat162float(h0);
    float r1 = v1 - __bfloat162float(h1);
    __nv_bfloat162 hh; hh.x = h0; hh.y = h1;
    __nv_bfloat162 ll; ll.x = __float2bfloat16(r0); ll.y = __float2bfloat16(r1);
    hi = *(uint32_t*)&hh;
    lo = *(uint32_t*)&ll;
}
__device__ __forceinline__ void split1(float v, unsigned short& h, unsigned short& l) {
    __nv_bfloat16 hb = __float2bfloat16(v);
    float r = v - __bfloat162float(hb);
    __nv_bfloat16 lb = __float2bfloat16(r);
    h = *(unsigned short*)&hb;
    l = *(unsigned short*)&lb;
}

// ============================================================================
// K1: 1x1-conv projections via mma.sync (split-2 bf16).
//   out[i, n] = sum_c w[i,c] * x[c,n] + bias[i]
//   A = w (row-major), B = x^T (staged transposed in SMEM).
//   grid (3, 64, 4), block 256 (8 warps); tile 128 i x 64 n, k chunked by 64.
// ============================================================================
__global__ void __launch_bounds__(256, 1) proj_mma_kernel(
    const float* __restrict__ x,
    const float* __restrict__ tw, const float* __restrict__ tb,
    const float* __restrict__ pw, const float* __restrict__ pb,
    const float* __restrict__ gw, const float* __restrict__ gb)
{
    extern __shared__ char psm[];
    float* xs = (float*)(psm + PX_OFF);                       // [64][66] fp32, transposed x
    __nv_bfloat16* wsh = (__nv_bfloat16*)(psm + PWH_OFF);     // [128][68]
    __nv_bfloat16* wsl = (__nv_bfloat16*)(psm + PWL_OFF);
    unsigned short* sth = (unsigned short*)(psm + PX_OFF);    // stage hi [64][130] (reuse)
    unsigned short* stl = (unsigned short*)(psm + PWH_OFF);   // stage lo [64][130]

    const int p  = blockIdx.x;
    const int n0 = blockIdx.y * 64;
    const int b  = blockIdx.z;
    const float* w    = (p == 0) ? tw : (p == 1) ? pw : gw;
    const float* bias = (p == 0) ? tb : (p == 1) ? pb : gb;

    const int tid  = threadIdx.x;
    const int wrp  = tid >> 5;
    const int lane = tid & 31;
    const int qrow = lane >> 2;
    const int qcol = lane & 3;
    const int i0   = 16 * wrp + qrow;

    float acc[8][4];
#pragma unroll
    for (int i = 0; i < 8; i++)
#pragma unroll
        for (int j = 0; j < 4; j++) acc[i][j] = 0.f;

    for (int c0 = 0; c0 < CN; c0 += 64) {
        __syncthreads();
        // x chunk -> transposed fp32 SMEM
#pragma unroll
        for (int r = 0; r < 4; r++) {
            int fid = tid + (r << 8);
            int cc = fid >> 4, n4 = fid & 15;
            float4 v = *(const float4*)(x + ((size_t)b * CN + c0 + cc) * HWN + n0 + 4 * n4);
            xs[(4 * n4 + 0) * 66 + cc] = v.x;
            xs[(4 * n4 + 1) * 66 + cc] = v.y;
            xs[(4 * n4 + 2) * 66 + cc] = v.z;
            xs[(4 * n4 + 3) * 66 + cc] = v.w;
        }
        // w chunk -> split bf16 hi/lo SMEM
#pragma unroll
        for (int r = 0; r < 8; r++) {
            int fid = tid + (r << 8);
            int ii = fid >> 4, cg = fid & 15;
            float4 v = *(const float4*)(w + (size_t)ii * CN + c0 + 4 * cg);
            uint32_t h0, l0, h1, l1;
            split2(v.x, v.y, h0, l0);
            split2(v.z, v.w, h1, l1);
            *(uint32_t*)&wsh[ii * 68 + 4 * cg]     = h0;
            *(uint32_t*)&wsh[ii * 68 + 4 * cg + 2] = h1;
            *(uint32_t*)&wsl[ii * 68 + 4 * cg]     = l0;
            *(uint32_t*)&wsl[ii * 68 + 4 * cg + 2] = l1;
        }
        __syncthreads();

        // A fragments (4 k-steps) in registers
        uint32_t ah[4][4], al[4][4];
#pragma unroll
        for (int ks = 0; ks < 4; ks++) {
            int k = 16 * ks + 2 * qcol;
            ah[ks][0] = *(uint32_t*)&wsh[(i0)     * 68 + k];
            ah[ks][1] = *(uint32_t*)&wsh[(i0 + 8) * 68 + k];
            ah[ks][2] = *(uint32_t*)&wsh[(i0)     * 68 + k + 8];
            ah[ks][3] = *(uint32_t*)&wsh[(i0 + 8) * 68 + k + 8];
            al[ks][0] = *(uint32_t*)&wsl[(i0)     * 68 + k];
            al[ks][1] = *(uint32_t*)&wsl[(i0 + 8) * 68 + k];
            al[ks][2] = *(uint32_t*)&wsl[(i0)     * 68 + k + 8];
            al[ks][3] = *(uint32_t*)&wsl[(i0 + 8) * 68 + k + 8];
        }
#pragma unroll
        for (int ks = 0; ks < 4; ks++) {
#pragma unroll
            for (int nt = 0; nt < 8; nt++) {
                const float* xr = &xs[(8 * nt + qrow) * 66 + 16 * ks + 2 * qcol];
                float2 fa = *(const float2*)xr;
                float2 fb = *(const float2*)(xr + 8);
                uint32_t bh0, bl0, bh1, bl1;
                split2(fa.x, fa.y, bh0, bl0);
                split2(fb.x, fb.y, bh1, bl1);
                mma_bf16(acc[nt][0], acc[nt][1], acc[nt][2], acc[nt][3],
                         ah[ks][0], ah[ks][1], ah[ks][2], ah[ks][3], bh0, bh1);
                mma_bf16(acc[nt][0], acc[nt][1], acc[nt][2], acc[nt][3],
                         ah[ks][0], ah[ks][1], ah[ks][2], ah[ks][3], bl0, bl1);
                mma_bf16(acc[nt][0], acc[nt][1], acc[nt][2], acc[nt][3],
                         al[ks][0], al[ks][1], al[ks][2], al[ks][3], bh0, bh1);
            }
        }
    }

    float bb0 = bias[i0];
    float bb1 = bias[i0 + 8];

    if (p < 2) {
        // stage [n][i] bf16 hi/lo, then coalesced copy
        __syncthreads();
#pragma unroll
        for (int nt = 0; nt < 8; nt++) {
            int n = 8 * nt + 2 * qcol;
            float v0 = acc[nt][0] + bb0, v1 = acc[nt][1] + bb0;
            float v2 = acc[nt][2] + bb1, v3 = acc[nt][3] + bb1;
            unsigned short h, l;
            split1(v0, h, l); sth[n * 130 + i0] = h;           stl[n * 130 + i0] = l;
            split1(v1, h, l); sth[(n + 1) * 130 + i0] = h;     stl[(n + 1) * 130 + i0] = l;
            split1(v2, h, l); sth[n * 130 + i0 + 8] = h;       stl[n * 130 + i0 + 8] = l;
            split1(v3, h, l); sth[(n + 1) * 130 + i0 + 8] = h; stl[(n + 1) * 130 + i0 + 8] = l;
        }
        __syncthreads();
        __nv_bfloat16* oh = (p == 0) ? gQh : gKh;
        __nv_bfloat16* ol = (p == 0) ? gQl : gKl;
#pragma unroll
        for (int r = 0; r < 16; r++) {
            int t = tid + (r << 8);               // 0..4095
            int row = t >> 6, w32 = t & 63;       // 64 rows x 64 uint32 (128 bf16)
            uint32_t hv = *(uint32_t*)&sth[row * 130 + 2 * w32];
            uint32_t lv = *(uint32_t*)&stl[row * 130 + 2 * w32];
            size_t gb_ = ((size_t)b * HWN + n0 + row) * DN + 2 * w32;
            *(uint32_t*)(oh + gb_) = hv;
            *(uint32_t*)(ol + gb_) = lv;
        }
    } else {
        // g -> [d][m]: n pairs contiguous, direct writes
#pragma unroll
        for (int nt = 0; nt < 8; nt++) {
            int n = n0 + 8 * nt + 2 * qcol;
            float v0 = acc[nt][0] + bb0, v1 = acc[nt][1] + bb0;
            float v2 = acc[nt][2] + bb1, v3 = acc[nt][3] + bb1;
            uint32_t h01, l01, h23, l23;
            split2(v0, v1, h01, l01);
            split2(v2, v3, h23, l23);
            size_t ba = ((size_t)b * DN + i0) * HWN + n;
            size_t bc = ((size_t)b * DN + i0 + 8) * HWN + n;
            *(uint32_t*)(gVh + ba) = h01;
            *(uint32_t*)(gVl + ba) = l01;
            *(uint32_t*)(gVh + bc) = h23;
            *(uint32_t*)(gVl + bc) = l23;
        }
    }
}

// ============================================================================
// K2: mma.sync bf16 split-2 flash attention (R4-validated).
// ============================================================================
__device__ __forceinline__ void load_kv_tile(uint32_t stg, int b, int m0, int tid) {
#pragma unroll
    for (int r = 0; r < 4; r++) {
        int ch = tid + (r << 8);
        int rw = ch >> 4;
        int kc = ch & 15;
        uint32_t dst = stg + rw * K_ROW + (kc << 4);
        size_t gi = (((size_t)b * HWN + m0 + rw) << 7) + (kc << 3);
        cp16(dst + KH_OFF, gKh + gi);
        cp16(dst + KL_OFF, gKl + gi);
    }
#pragma unroll
    for (int r = 0; r < 4; r++) {
        int ch = tid + (r << 8);
        int rw = ch >> 3;
        int mc = ch & 7;
        uint32_t dst = stg + rw * V_ROW + (mc << 4);
        size_t gi = (((size_t)b * DN + rw) << 12) + m0 + (mc << 3);
        cp16(dst + VH_OFF, gVh + gi);
        cp16(dst + VL_OFF, gVl + gi);
    }
}

__global__ void __launch_bounds__(256, 1) attn_mma_kernel()
{
    extern __shared__ char smem[];
    const uint32_t smb = smem_u32(smem);

    const int tid  = threadIdx.x;
    const int lane = tid & 31;
    const int wrp  = tid >> 5;
    const int qrow = lane >> 2;
    const int qcol = lane & 3;
    const int n0   = blockIdx.x * TM;
    const int b    = blockIdx.y;
    const int row0 = 16 * wrp + qrow;

    uint32_t qh[8][4], ql[8][4];
    {
        const size_t rbase = ((size_t)b * HWN + n0 + row0) * DN;
#pragma unroll
        for (int ks = 0; ks < 8; ks++) {
            int k0 = 16 * ks + 2 * qcol;
            qh[ks][0] = *(const uint32_t*)(gQh + rbase + k0);
            qh[ks][1] = *(const uint32_t*)(gQh + rbase + 8 * DN + k0);
            qh[ks][2] = *(const uint32_t*)(gQh + rbase + k0 + 8);
            qh[ks][3] = *(const uint32_t*)(gQh + rbase + 8 * DN + k0 + 8);
            ql[ks][0] = *(const uint32_t*)(gQl + rbase + k0);
            ql[ks][1] = *(const uint32_t*)(gQl + rbase + 8 * DN + k0);
            ql[ks][2] = *(const uint32_t*)(gQl + rbase + k0 + 8);
            ql[ks][3] = *(const uint32_t*)(gQl + rbase + 8 * DN + k0 + 8);
        }
    }

    float o[16][4];
#pragma unroll
    for (int i = 0; i < 16; i++)
#pragma unroll
        for (int j = 0; j < 4; j++) o[i][j] = 0.f;

    float rs0 = 0.f, rs1 = 0.f;

    load_kv_tile(smb, b, 0, tid);
    CP_COMMIT();

    for (int t = 0; t < 64; t++) {
        const uint32_t stg = smb + (uint32_t)(t & 1) * STG_SZ;
        __syncthreads();
        if (t + 1 < 64) {
            load_kv_tile(smb + (uint32_t)((t + 1) & 1) * STG_SZ, b, (t + 1) * TN, tid);
            CP_COMMIT();
            CP_WAIT1();
        } else {
            CP_WAIT0();
        }
        __syncthreads();

        uint32_t ph[8][2], pl[8][2];
#pragma unroll
        for (int nt = 0; nt < 8; nt++) {
            float c0 = 0.f, c1 = 0.f, c2 = 0.f, c3 = 0.f;
            const uint32_t krow = stg + (uint32_t)(8 * nt + qrow) * K_ROW + (uint32_t)(4 * qcol);
#pragma unroll
            for (int ks = 0; ks < 8; ks++) {
                uint32_t bh0 = lds32(krow + KH_OFF + 32 * ks);
                uint32_t bh1 = lds32(krow + KH_OFF + 32 * ks + 16);
                uint32_t bl0 = lds32(krow + KL_OFF + 32 * ks);
                uint32_t bl1 = lds32(krow + KL_OFF + 32 * ks + 16);
                mma_bf16(c0, c1, c2, c3, qh[ks][0], qh[ks][1], qh[ks][2], qh[ks][3], bh0, bh1);
                mma_bf16(c0, c1, c2, c3, qh[ks][0], qh[ks][1], qh[ks][2], qh[ks][3], bl0, bl1);
                mma_bf16(c0, c1, c2, c3, ql[ks][0], ql[ks][1], ql[ks][2], ql[ks][3], bh0, bh1);
            }
            float e0 = __expf(c0), e1 = __expf(c1);
            float e2 = __expf(c2), e3 = __expf(c3);
            rs0 += e0 + e1;
            rs1 += e2 + e3;
            split2(e0, e1, ph[nt][0], pl[nt][0]);
            split2(e2, e3, ph[nt][1], pl[nt][1]);
        }

#pragma unroll
        for (int ks = 0; ks < 4; ks++) {
            uint32_t ah0 = ph[2 * ks][0], ah1 = ph[2 * ks][1];
            uint32_t ah2 = ph[2 * ks + 1][0], ah3 = ph[2 * ks + 1][1];
            uint32_t al0 = pl[2 * ks][0], al1 = pl[2 * ks][1];
            uint32_t al2 = pl[2 * ks + 1][0], al3 = pl[2 * ks + 1][1];
            const uint32_t vcol = stg + (uint32_t)(32 * ks + 4 * qcol);
#pragma unroll
            for (int nt = 0; nt < 16; nt++) {
                const uint32_t vrow = vcol + (uint32_t)(8 * nt + qrow) * V_ROW;
                uint32_t bh0 = lds32(vrow + VH_OFF);
                uint32_t bh1 = lds32(vrow + VH_OFF + 16);
                uint32_t bl0 = lds32(vrow + VL_OFF);
                uint32_t bl1 = lds32(vrow + VL_OFF + 16);
                mma_bf16(o[nt][0], o[nt][1], o[nt][2], o[nt][3], ah0, ah1, ah2, ah3, bh0, bh1);
                mma_bf16(o[nt][0], o[nt][1], o[nt][2], o[nt][3], ah0, ah1, ah2, ah3, bl0, bl1);
                mma_bf16(o[nt][0], o[nt][1], o[nt][2], o[nt][3], al0, al1, al2, al3, bh0, bh1);
            }
        }
    }

    rs0 += __shfl_xor_sync(0xffffffffu, rs0, 1);
    rs0 += __shfl_xor_sync(0xffffffffu, rs0, 2);
    rs1 += __shfl_xor_sync(0xffffffffu, rs1, 1);
    rs1 += __shfl_xor_sync(0xffffffffu, rs1, 2);
    float inv0 = 1.f / rs0;
    float inv1 = 1.f / rs1;

    float* y0 = d_Y + ((size_t)b * HWN + n0 + row0) * DN + 2 * qcol;
    float* y1 = y0 + 8 * DN;
#pragma unroll
    for (int nt = 0; nt < 16; nt++) {
        *(float2*)(y0 + 8 * nt) = make_float2(o[nt][0] * inv0, o[nt][1] * inv0);
        *(float2*)(y1 + 8 * nt) = make_float2(o[nt][2] * inv1, o[nt][3] * inv1);
    }
}

// ============================================================================
// K3: wy = W*y + b via mma.sync (split-2), with fused BN partial statistics.
// ============================================================================
__global__ void __launch_bounds__(256, 1) wgemm_mma_kernel(
    const float* __restrict__ Ww, const float* __restrict__ Wb)
{
    __shared__ float ys[64 * 132];

    const int c0 = blockIdx.x * 128;
    const int n0 = blockIdx.y * 64;
    const int b  = blockIdx.z;
    const int part = blockIdx.y * 4 + blockIdx.z;     // 0..255

    const int tid  = threadIdx.x;
    const int lane = tid & 31;
    const int wrp  = tid >> 5;
    const int qrow = lane >> 2;
    const int qcol = lane & 3;
    const int c    = c0 + 16 * wrp + qrow;

    // stage y tile (fp32, [n][i], no transpose)
#pragma unroll
    for (int r = 0; r < 8; r++) {
        int fid = tid + (r << 8);
        int nn = fid >> 5, ig = fid & 31;
        float4 v = *(const float4*)(d_Y + ((size_t)b * HWN + n0 + nn) * DN + 4 * ig);
        *(float4*)&ys[nn * 132 + 4 * ig] = v;
    }
    __syncthreads();

    float acc[8][4];
#pragma unroll
    for (int i = 0; i < 8; i++)
#pragma unroll
        for (int j = 0; j < 4; j++) acc[i][j] = 0.f;

#pragma unroll
    for (int ks = 0; ks < 8; ks++) {
        int k = 16 * ks + 2 * qcol;
        float2 a0 = *(const float2*)(Ww + (size_t)c * DN + k);
        float2 a1 = *(const float2*)(Ww + (size_t)(c + 8) * DN + k);
        float2 a2 = *(const float2*)(Ww + (size_t)c * DN + k + 8);
        float2 a3 = *(const float2*)(Ww + (size_t)(c + 8) * DN + k + 8);
        uint32_t ah[4], al[4];
        split2(a0.x, a0.y, ah[0], al[0]);
        split2(a1.x, a1.y, ah[1], al[1]);
        split2(a2.x, a2.y, ah[2], al[2]);
        split2(a3.x, a3.y, ah[3], al[3]);
#pragma unroll
        for (int nt = 0; nt < 8; nt++) {
            const float* yr = &ys[(8 * nt + qrow) * 132 + k];
            float2 fa = *(const float2*)yr;
            float2 fb = *(const float2*)(yr + 8);
            uint32_t bh0, bl0, bh1, bl1;
            split2(fa.x, fa.y, bh0, bl0);
            split2(fb.x, fb.y, bh1, bl1);
            mma_bf16(acc[nt][0], acc[nt][1], acc[nt][2], acc[nt][3],
                     ah[0], ah[1], ah[2], ah[3], bh0, bh1);
            mma_bf16(acc[nt][0], acc[nt][1], acc[nt][2], acc[nt][3],
                     ah[0], ah[1], ah[2], ah[3], bl0, bl1);
            mma_bf16(acc[nt][0], acc[nt][1], acc[nt][2], acc[nt][3],
                     al[0], al[1], al[2], al[3], bh0, bh1);
        }
    }

    // epilogue: bias + store + BN partial stats
    float bb0 = Wb[c], bb1 = Wb[c + 8];
    float s0 = 0.f, q0 = 0.f, s1 = 0.f, q1 = 0.f;
#pragma unroll
    for (int nt = 0; nt < 8; nt++) {
        int n = n0 + 8 * nt + 2 * qcol;
        float v0 = acc[nt][0] + bb0, v1 = acc[nt][1] + bb0;
        float v2 = acc[nt][2] + bb1, v3 = acc[nt][3] + bb1;
        s0 += v0 + v1; q0 += v0 * v0 + v1 * v1;
        s1 += v2 + v3; q1 += v2 * v2 + v3 * v3;
        *(float2*)(d_WY + ((size_t)b * CN + c) * HWN + n)     = make_float2(v0, v1);
        *(float2*)(d_WY + ((size_t)b * CN + c + 8) * HWN + n) = make_float2(v2, v3);
    }
    s0 += __shfl_xor_sync(0xffffffffu, s0, 1);
    s0 += __shfl_xor_sync(0xffffffffu, s0, 2);
    q0 += __shfl_xor_sync(0xffffffffu, q0, 1);
    q0 += __shfl_xor_sync(0xffffffffu, q0, 2);
    s1 += __shfl_xor_sync(0xffffffffu, s1, 1);
    s1 += __shfl_xor_sync(0xffffffffu, s1, 2);
    q1 += __shfl_xor_sync(0xffffffffu, q1, 1);
    q1 += __shfl_xor_sync(0xffffffffu, q1, 2);
    if (qcol == 0) {
        gPS[c * 256 + part] = s0;
        gPQ[c * 256 + part] = q0;
        gPS[(c + 8) * 256 + part] = s1;
        gPQ[(c + 8) * 256 + part] = q1;
    }
}

// ============================================================================
// K4: BN stats finalize from partials.
// ============================================================================
__global__ void bnfinal_kernel()
{
    const int c = blockIdx.x;
    const int tid = threadIdx.x;
    __shared__ float sh[256], sh2[256];
    sh[tid]  = gPS[c * 256 + tid];
    sh2[tid] = gPQ[c * 256 + tid];
    __syncthreads();
    for (int off = 128; off > 0; off >>= 1) {
        if (tid < off) { sh[tid] += sh[tid + off]; sh2[tid] += sh2[tid + off]; }
        __syncthreads();
    }
    if (tid == 0) {
        const float invN = 1.f / (float)(BN * HWN);
        float mean = sh[0] * invN;
        float var  = sh2[0] * invN - mean * mean;
        d_MEAN[c] = mean;
        d_RSTD[c] = rsqrtf(var + 1e-5f);
    }
}

// ============================================================================
// K5: finalize: out = gamma*(wy-mean)*rstd + beta + x
// ============================================================================
__global__ void finalize_kernel(const float* __restrict__ x,
                                const float* __restrict__ gamma,
                                const float* __restrict__ beta,
                                float* __restrict__ out)
{
    int idx = blockIdx.x * blockDim.x + threadIdx.x;
    int c = (idx >> 10) & 255;
    float4 wv = ((const float4*)d_WY)[idx];
    float4 xv = ((const float4*)x)[idx];
    float g  = gamma[c] * d_RSTD[c];
    float m  = d_MEAN[c];
    float bt = beta[c];
    float4 o;
    o.x = (wv.x - m) * g + bt + xv.x;
    o.y = (wv.y - m) * g + bt + xv.y;
    o.z = (wv.z - m) * g + bt + xv.z;
    o.w = (wv.w - m) * g + bt + xv.w;
    ((float4*)out)[idx] = o;
}

// ============================================================================
extern "C" void kernel_launch(void* const* d_in, const int* in_sizes, int n_in,
                              void* d_out, int out_size)
{
    const float* x     = (const float*)d_in[0];
    const float* tw    = (const float*)d_in[1];
    const float* tb    = (const float*)d_in[2];
    const float* pw    = (const float*)d_in[3];
    const float* pb    = (const float*)d_in[4];
    const float* gw    = (const float*)d_in[5];
    const float* gb    = (const float*)d_in[6];
    const float* Ww    = (const float*)d_in[7];
    const float* Wb    = (const float*)d_in[8];
    const float* gamma = (const float*)d_in[9];
    const float* beta  = (const float*)d_in[10];
    float* out = (float*)d_out;

    cudaFuncSetAttribute(proj_mma_kernel, cudaFuncAttributeMaxDynamicSharedMemorySize, PRJ_SMEM);
    cudaFuncSetAttribute(attn_mma_kernel, cudaFuncAttributeMaxDynamicSharedMemorySize, ATTN_SMEM);

    dim3 g1(3, HWN / 64, BN);
    proj_mma_kernel<<<g1, 256, PRJ_SMEM>>>(x, tw, tb, pw, pb, gw, gb);

    dim3 g2(HWN / TM, BN);
    attn_mma_kernel<<<g2, 256, ATTN_SMEM>>>();

    dim3 g3(2, HWN / 64, BN);
    wgemm_mma_kernel<<<g3, 256>>>(Ww, Wb);

    bnfinal_kernel<<<CN, 256>>>();

    finalize_kernel<<<(BN * CN * HWN / 4) / 256, 256>>>(x, gamma, beta, out);
}

// round 7
// speedup vs baseline: 4.1858x; 1.1332x over previous
#include <cuda_runtime.h>
#include <cuda_bf16.h>
#include <math.h>
#include <stdint.h>

#define BN   4
#define CN   256
#define HWN  4096
#define DN   128
#define TM   128            // queries per CTA (attention)
#define TN   64             // keys per tile
#define LOG2E 1.4426950408889634f

// attention smem stage layout (bytes)
#define K_ROW   272
#define V_ROW   144
#define KH_OFF  0
#define KL_OFF  (64 * K_ROW)
#define VH_OFF  (2 * 64 * K_ROW)
#define VL_OFF  (2 * 64 * K_ROW + 128 * V_ROW)
#define STG_SZ  (2 * 64 * K_ROW + 2 * 128 * V_ROW)   // 71680
#define ATTN_SMEM (2 * STG_SZ)                        // 143360

// proj smem (bytes): x planes [64][144B], w planes [128][144B]
#define PXH 0
#define PXL 9216
#define PWH 18432
#define PWL 36864
#define PRJ_SMEM 55296

// wgemm smem: y planes [64][272B]
#define WYH 0
#define WYL 17408
#define WG_SMEM 34816

// -------------------- scratch --------------------
__device__ __align__(128) __nv_bfloat16 gXh[BN * HWN * CN];  // x^T hi [b][n][c]
__device__ __align__(128) __nv_bfloat16 gXl[BN * HWN * CN];
__device__ __align__(128) __nv_bfloat16 gWh[3 * DN * CN];    // proj weights hi [p][i][c]
__device__ __align__(128) __nv_bfloat16 gWl[3 * DN * CN];
__device__ __align__(128) __nv_bfloat16 gWWh[CN * DN];       // W hi [c][i]
__device__ __align__(128) __nv_bfloat16 gWWl[CN * DN];
__device__ __align__(128) __nv_bfloat16 gQh[BN * HWN * DN];  // theta hi [b][n][k]
__device__ __align__(128) __nv_bfloat16 gQl[BN * HWN * DN];
__device__ __align__(128) __nv_bfloat16 gKh[BN * HWN * DN];  // phi(scaled) hi [b][m][k]
__device__ __align__(128) __nv_bfloat16 gKl[BN * HWN * DN];
__device__ __align__(128) __nv_bfloat16 gVh[BN * DN * HWN];  // g hi [b][d][m]
__device__ __align__(128) __nv_bfloat16 gVl[BN * DN * HWN];
__device__ __align__(128) __nv_bfloat16 gYh[BN * HWN * DN];  // attn out hi [b][n][i]
__device__ __align__(128) __nv_bfloat16 gYl[BN * HWN * DN];
__device__ __align__(128) float d_WY[BN * CN * HWN];         // [b][c][n]
__device__ float gPS[CN * 256];
__device__ float gPQ[CN * 256];
__device__ float d_MEAN[CN];
__device__ float d_RSTD[CN];

// ======================= helpers =======================
__device__ __forceinline__ uint32_t smem_u32(const void* p) {
    uint32_t a;
    asm("{ .reg .u64 t; cvta.to.shared.u64 t, %1; cvt.u32.u64 %0, t; }" : "=r"(a) : "l"(p));
    return a;
}
__device__ __forceinline__ void cp16(uint32_t dst, const void* src) {
    asm volatile("cp.async.cg.shared.global [%0], [%1], 16;" :: "r"(dst), "l"(src));
}
#define CP_COMMIT() asm volatile("cp.async.commit_group;" ::: "memory")
#define CP_WAIT0()  asm volatile("cp.async.wait_group 0;" ::: "memory")
#define CP_WAIT1()  asm volatile("cp.async.wait_group 1;" ::: "memory")

__device__ __forceinline__ void mma_bf16(float& c0, float& c1, float& c2, float& c3,
                                         uint32_t a0, uint32_t a1, uint32_t a2, uint32_t a3,
                                         uint32_t b0, uint32_t b1) {
    asm volatile("mma.sync.aligned.m16n8k16.row.col.f32.bf16.bf16.f32 "
                 "{%0,%1,%2,%3}, {%4,%5,%6,%7}, {%8,%9}, {%0,%1,%2,%3};"
                 : "+f"(c0), "+f"(c1), "+f"(c2), "+f"(c3)
                 : "r"(a0), "r"(a1), "r"(a2), "r"(a3), "r"(b0), "r"(b1));
}
__device__ __forceinline__ uint32_t lds32(uint32_t addr) {
    uint32_t v;
    asm volatile("ld.shared.b32 %0, [%1];" : "=r"(v) : "r"(addr));
    return v;
}
__device__ __forceinline__ void split2(float v0, float v1, uint32_t& hi, uint32_t& lo) {
    __nv_bfloat16 h0 = __float2bfloat16(v0);
    __nv_bfloat16 h1 = __float2bfloat16(v1);
    float r0 = v0 - __bfloat162float(h0);
    float r1 = v1 - __bfloat162float(h1);
    __nv_bfloat162 hh; hh.x = h0; hh.y = h1;
    __nv_bfloat162 ll; ll.x = __float2bfloat16(r0); ll.y = __float2bfloat16(r1);
    hi = *(uint32_t*)&hh;
    lo = *(uint32_t*)&ll;
}
__device__ __forceinline__ void split1(float v, unsigned short& h, unsigned short& l) {
    __nv_bfloat16 hb = __float2bfloat16(v);
    float r = v - __bfloat162float(hb);
    __nv_bfloat16 lb = __float2bfloat16(r);
    h = *(unsigned short*)&hb;
    l = *(unsigned short*)&lb;
}

// ============================================================================
// K0: pre-split all weights to bf16 hi/lo. grid 256, block 256.
// ============================================================================
__global__ void wsplit_kernel(const float* __restrict__ tw, const float* __restrict__ pw,
                              const float* __restrict__ gw, const float* __restrict__ Ww)
{
    int idx = blockIdx.x * 256 + threadIdx.x;       // 65536 float2 slots
    if (idx < 49152) {
        int p = idx / 16384, r = idx - p * 16384;
        const float* s = (p == 0) ? tw : (p == 1) ? pw : gw;
        float2 v = *(const float2*)(s + 2 * r);
        uint32_t hi, lo;
        split2(v.x, v.y, hi, lo);
        *(uint32_t*)(gWh + p * 32768 + 2 * r) = hi;
        *(uint32_t*)(gWl + p * 32768 + 2 * r) = lo;
    } else {
        int r = idx - 49152;                        // 16384 float2 of Ww
        float2 v = *(const float2*)(Ww + 2 * r);
        uint32_t hi, lo;
        split2(v.x, v.y, hi, lo);
        *(uint32_t*)(gWWh + 2 * r) = hi;
        *(uint32_t*)(gWWl + 2 * r) = lo;
    }
}

// ============================================================================
// K0b: transpose+split x -> xT hi/lo [b][n][c]. grid (64, 4, 4), block 256.
// ============================================================================
__global__ void xsplit_kernel(const float* __restrict__ x)
{
    __shared__ float xs[64][68];
    const int n0 = blockIdx.x * 64;
    const int c0 = blockIdx.y * 64;
    const int b  = blockIdx.z;
    const int tid = threadIdx.x;
#pragma unroll
    for (int r = 0; r < 4; r++) {
        int fid = tid + (r << 8);
        int cc = fid >> 4, n4 = fid & 15;
        float4 v = *(const float4*)(x + ((size_t)b * CN + c0 + cc) * HWN + n0 + 4 * n4);
        *(float4*)&xs[cc][4 * n4] = v;
    }
    __syncthreads();
#pragma unroll
    for (int r = 0; r < 8; r++) {
        int fid = tid + (r << 8);
        int n = fid >> 5, cp = fid & 31;
        float a  = xs[2 * cp][n];
        float bb = xs[2 * cp + 1][n];
        uint32_t hi, lo;
        split2(a, bb, hi, lo);
        size_t gi = ((size_t)b * HWN + n0 + n) * CN + c0 + 2 * cp;
        *(uint32_t*)(gXh + gi) = hi;
        *(uint32_t*)(gXl + gi) = lo;
    }
}

// ============================================================================
// K1: projections via mma.sync, all operands pre-split (no mainloop ALU).
//   grid (3, 64, 4), block 256. Tile 128 i x 64 n, k chunks of 64.
// ============================================================================
__global__ void __launch_bounds__(256) proj_mma_kernel(
    const float* __restrict__ tb, const float* __restrict__ pb, const float* __restrict__ gb)
{
    extern __shared__ char psm[];
    const uint32_t smb = smem_u32(psm);
    unsigned short* sth = (unsigned short*)(psm);            // stage hi [64][130]
    unsigned short* stl = (unsigned short*)(psm + 16640);    // stage lo [64][130]

    const int p  = blockIdx.x;
    const int n0 = blockIdx.y * 64;
    const int b  = blockIdx.z;
    const float* bias = (p == 0) ? tb : (p == 1) ? pb : gb;

    const int tid  = threadIdx.x;
    const int wrp  = tid >> 5;
    const int lane = tid & 31;
    const int qrow = lane >> 2;
    const int qcol = lane & 3;
    const int i0   = 16 * wrp + qrow;

    float acc[8][4];
#pragma unroll
    for (int i = 0; i < 8; i++)
#pragma unroll
        for (int j = 0; j < 4; j++) acc[i][j] = 0.f;

    for (int c0 = 0; c0 < CN; c0 += 64) {
        __syncthreads();
        // stage x planes: 2 x 64 rows x 8 chunks
#pragma unroll
        for (int r = 0; r < 4; r++) {
            int fid = tid + (r << 8);
            int pl = fid >> 9, rem = fid & 511;
            int row = rem >> 3, ch = rem & 7;
            const __nv_bfloat16* src = (pl ? gXl : gXh) +
                ((size_t)b * HWN + n0 + row) * CN + c0 + ch * 8;
            cp16(smb + (pl ? PXL : PXH) + row * 144 + ch * 16, src);
        }
        // stage w planes: 2 x 128 rows x 8 chunks
#pragma unroll
        for (int r = 0; r < 8; r++) {
            int fid = tid + (r << 8);
            int pl = fid >> 10, rem = fid & 1023;
            int row = rem >> 3, ch = rem & 7;
            const __nv_bfloat16* src = (pl ? gWl : gWh) +
                (size_t)p * 32768 + row * CN + c0 + ch * 8;
            cp16(smb + (pl ? PWL : PWH) + row * 144 + ch * 16, src);
        }
        CP_COMMIT();
        CP_WAIT0();
        __syncthreads();

        // A fragments
        uint32_t ah[4][4], al[4][4];
#pragma unroll
        for (int ks = 0; ks < 4; ks++) {
            uint32_t ko = 32 * ks + 4 * qcol;
            ah[ks][0] = lds32(smb + PWH + i0 * 144 + ko);
            ah[ks][1] = lds32(smb + PWH + (i0 + 8) * 144 + ko);
            ah[ks][2] = lds32(smb + PWH + i0 * 144 + ko + 16);
            ah[ks][3] = lds32(smb + PWH + (i0 + 8) * 144 + ko + 16);
            al[ks][0] = lds32(smb + PWL + i0 * 144 + ko);
            al[ks][1] = lds32(smb + PWL + (i0 + 8) * 144 + ko);
            al[ks][2] = lds32(smb + PWL + i0 * 144 + ko + 16);
            al[ks][3] = lds32(smb + PWL + (i0 + 8) * 144 + ko + 16);
        }
#pragma unroll
        for (int ks = 0; ks < 4; ks++) {
#pragma unroll
            for (int nt = 0; nt < 8; nt++) {
                uint32_t ro = (8 * nt + qrow) * 144 + 32 * ks + 4 * qcol;
                uint32_t bh0 = lds32(smb + PXH + ro);
                uint32_t bh1 = lds32(smb + PXH + ro + 16);
                uint32_t bl0 = lds32(smb + PXL + ro);
                uint32_t bl1 = lds32(smb + PXL + ro + 16);
                mma_bf16(acc[nt][0], acc[nt][1], acc[nt][2], acc[nt][3],
                         ah[ks][0], ah[ks][1], ah[ks][2], ah[ks][3], bh0, bh1);
                mma_bf16(acc[nt][0], acc[nt][1], acc[nt][2], acc[nt][3],
                         ah[ks][0], ah[ks][1], ah[ks][2], ah[ks][3], bl0, bl1);
                mma_bf16(acc[nt][0], acc[nt][1], acc[nt][2], acc[nt][3],
                         al[ks][0], al[ks][1], al[ks][2], al[ks][3], bh0, bh1);
            }
        }
    }

    const float bb0 = bias[i0];
    const float bb1 = bias[i0 + 8];
    const float sc  = (p == 1) ? LOG2E : 1.f;     // fold ln2 into phi -> exp2 in attn

    if (p < 2) {
        __syncthreads();
#pragma unroll
        for (int nt = 0; nt < 8; nt++) {
            int n = 8 * nt + 2 * qcol;
            float v0 = (acc[nt][0] + bb0) * sc, v1 = (acc[nt][1] + bb0) * sc;
            float v2 = (acc[nt][2] + bb1) * sc, v3 = (acc[nt][3] + bb1) * sc;
            unsigned short h, l;
            split1(v0, h, l); sth[n * 130 + i0] = h;           stl[n * 130 + i0] = l;
            split1(v1, h, l); sth[(n + 1) * 130 + i0] = h;     stl[(n + 1) * 130 + i0] = l;
            split1(v2, h, l); sth[n * 130 + i0 + 8] = h;       stl[n * 130 + i0 + 8] = l;
            split1(v3, h, l); sth[(n + 1) * 130 + i0 + 8] = h; stl[(n + 1) * 130 + i0 + 8] = l;
        }
        __syncthreads();
        __nv_bfloat16* oh = (p == 0) ? gQh : gKh;
        __nv_bfloat16* ol = (p == 0) ? gQl : gKl;
#pragma unroll
        for (int r = 0; r < 16; r++) {
            int t = tid + (r << 8);
            int row = t >> 6, w32 = t & 63;
            uint32_t hv = *(uint32_t*)&sth[row * 130 + 2 * w32];
            uint32_t lv = *(uint32_t*)&stl[row * 130 + 2 * w32];
            size_t gb_ = ((size_t)b * HWN + n0 + row) * DN + 2 * w32;
            *(uint32_t*)(oh + gb_) = hv;
            *(uint32_t*)(ol + gb_) = lv;
        }
    } else {
#pragma unroll
        for (int nt = 0; nt < 8; nt++) {
            int n = n0 + 8 * nt + 2 * qcol;
            float v0 = acc[nt][0] + bb0, v1 = acc[nt][1] + bb0;
            float v2 = acc[nt][2] + bb1, v3 = acc[nt][3] + bb1;
            uint32_t h01, l01, h23, l23;
            split2(v0, v1, h01, l01);
            split2(v2, v3, h23, l23);
            size_t ba = ((size_t)b * DN + i0) * HWN + n;
            size_t bc = ((size_t)b * DN + i0 + 8) * HWN + n;
            *(uint32_t*)(gVh + ba) = h01;
            *(uint32_t*)(gVl + ba) = l01;
            *(uint32_t*)(gVh + bc) = h23;
            *(uint32_t*)(gVl + bc) = l23;
        }
    }
}

// ============================================================================
// K2: mma.sync bf16 split-2 flash attention; outputs Y as bf16 hi/lo planes.
// ============================================================================
__device__ __forceinline__ void load_kv_tile(uint32_t stg, int b, int m0, int tid) {
#pragma unroll
    for (int r = 0; r < 4; r++) {
        int ch = tid + (r << 8);
        int rw = ch >> 4;
        int kc = ch & 15;
        uint32_t dst = stg + rw * K_ROW + (kc << 4);
        size_t gi = (((size_t)b * HWN + m0 + rw) << 7) + (kc << 3);
        cp16(dst + KH_OFF, gKh + gi);
        cp16(dst + KL_OFF, gKl + gi);
    }
#pragma unroll
    for (int r = 0; r < 4; r++) {
        int ch = tid + (r << 8);
        int rw = ch >> 3;
        int mc = ch & 7;
        uint32_t dst = stg + rw * V_ROW + (mc << 4);
        size_t gi = (((size_t)b * DN + rw) << 12) + m0 + (mc << 3);
        cp16(dst + VH_OFF, gVh + gi);
        cp16(dst + VL_OFF, gVl + gi);
    }
}

__global__ void __launch_bounds__(256, 1) attn_mma_kernel()
{
    extern __shared__ char smem[];
    const uint32_t smb = smem_u32(smem);

    const int tid  = threadIdx.x;
    const int lane = tid & 31;
    const int wrp  = tid >> 5;
    const int qrow = lane >> 2;
    const int qcol = lane & 3;
    const int n0   = blockIdx.x * TM;
    const int b    = blockIdx.y;
    const int row0 = 16 * wrp + qrow;

    uint32_t qh[8][4], ql[8][4];
    {
        const size_t rbase = ((size_t)b * HWN + n0 + row0) * DN;
#pragma unroll
        for (int ks = 0; ks < 8; ks++) {
            int k0 = 16 * ks + 2 * qcol;
            qh[ks][0] = *(const uint32_t*)(gQh + rbase + k0);
            qh[ks][1] = *(const uint32_t*)(gQh + rbase + 8 * DN + k0);
            qh[ks][2] = *(const uint32_t*)(gQh + rbase + k0 + 8);
            qh[ks][3] = *(const uint32_t*)(gQh + rbase + 8 * DN + k0 + 8);
            ql[ks][0] = *(const uint32_t*)(gQl + rbase + k0);
            ql[ks][1] = *(const uint32_t*)(gQl + rbase + 8 * DN + k0);
            ql[ks][2] = *(const uint32_t*)(gQl + rbase + k0 + 8);
            ql[ks][3] = *(const uint32_t*)(gQl + rbase + 8 * DN + k0 + 8);
        }
    }

    float o[16][4];
#pragma unroll
    for (int i = 0; i < 16; i++)
#pragma unroll
        for (int j = 0; j < 4; j++) o[i][j] = 0.f;

    float rs0 = 0.f, rs1 = 0.f;

    load_kv_tile(smb, b, 0, tid);
    CP_COMMIT();

    for (int t = 0; t < 64; t++) {
        const uint32_t stg = smb + (uint32_t)(t & 1) * STG_SZ;
        __syncthreads();
        if (t + 1 < 64) {
            load_kv_tile(smb + (uint32_t)((t + 1) & 1) * STG_SZ, b, (t + 1) * TN, tid);
            CP_COMMIT();
            CP_WAIT1();
        } else {
            CP_WAIT0();
        }
        __syncthreads();

        uint32_t ph[8][2], pl[8][2];
#pragma unroll
        for (int nt = 0; nt < 8; nt++) {
            float c0 = 0.f, c1 = 0.f, c2 = 0.f, c3 = 0.f;
            const uint32_t krow = stg + (uint32_t)(8 * nt + qrow) * K_ROW + (uint32_t)(4 * qcol);
#pragma unroll
            for (int ks = 0; ks < 8; ks++) {
                uint32_t bh0 = lds32(krow + KH_OFF + 32 * ks);
                uint32_t bh1 = lds32(krow + KH_OFF + 32 * ks + 16);
                uint32_t bl0 = lds32(krow + KL_OFF + 32 * ks);
                uint32_t bl1 = lds32(krow + KL_OFF + 32 * ks + 16);
                mma_bf16(c0, c1, c2, c3, qh[ks][0], qh[ks][1], qh[ks][2], qh[ks][3], bh0, bh1);
                mma_bf16(c0, c1, c2, c3, qh[ks][0], qh[ks][1], qh[ks][2], qh[ks][3], bl0, bl1);
                mma_bf16(c0, c1, c2, c3, ql[ks][0], ql[ks][1], ql[ks][2], ql[ks][3], bh0, bh1);
            }
            // phi pre-scaled by log2(e): p = exp2(f*log2e) = e^f
            float e0 = exp2f(c0), e1 = exp2f(c1);
            float e2 = exp2f(c2), e3 = exp2f(c3);
            rs0 += e0 + e1;
            rs1 += e2 + e3;
            split2(e0, e1, ph[nt][0], pl[nt][0]);
            split2(e2, e3, ph[nt][1], pl[nt][1]);
        }

#pragma unroll
        for (int ks = 0; ks < 4; ks++) {
            uint32_t ah0 = ph[2 * ks][0], ah1 = ph[2 * ks][1];
            uint32_t ah2 = ph[2 * ks + 1][0], ah3 = ph[2 * ks + 1][1];
            uint32_t al0 = pl[2 * ks][0], al1 = pl[2 * ks][1];
            uint32_t al2 = pl[2 * ks + 1][0], al3 = pl[2 * ks + 1][1];
            const uint32_t vcol = stg + (uint32_t)(32 * ks + 4 * qcol);
#pragma unroll
            for (int nt = 0; nt < 16; nt++) {
                const uint32_t vrow = vcol + (uint32_t)(8 * nt + qrow) * V_ROW;
                uint32_t bh0 = lds32(vrow + VH_OFF);
                uint32_t bh1 = lds32(vrow + VH_OFF + 16);
                uint32_t bl0 = lds32(vrow + VL_OFF);
                uint32_t bl1 = lds32(vrow + VL_OFF + 16);
                mma_bf16(o[nt][0], o[nt][1], o[nt][2], o[nt][3], ah0, ah1, ah2, ah3, bh0, bh1);
                mma_bf16(o[nt][0], o[nt][1], o[nt][2], o[nt][3], ah0, ah1, ah2, ah3, bl0, bl1);
                mma_bf16(o[nt][0], o[nt][1], o[nt][2], o[nt][3], al0, al1, al2, al3, bh0, bh1);
            }
        }
    }

    rs0 += __shfl_xor_sync(0xffffffffu, rs0, 1);
    rs0 += __shfl_xor_sync(0xffffffffu, rs0, 2);
    rs1 += __shfl_xor_sync(0xffffffffu, rs1, 1);
    rs1 += __shfl_xor_sync(0xffffffffu, rs1, 2);
    float inv0 = 1.f / rs0;
    float inv1 = 1.f / rs1;

    // store Y as bf16 hi/lo planes [b][n][i]
    const size_t y0 = ((size_t)b * HWN + n0 + row0) * DN + 2 * qcol;
    const size_t y1 = y0 + 8 * DN;
#pragma unroll
    for (int nt = 0; nt < 16; nt++) {
        uint32_t h0, l0, h1, l1;
        split2(o[nt][0] * inv0, o[nt][1] * inv0, h0, l0);
        split2(o[nt][2] * inv1, o[nt][3] * inv1, h1, l1);
        *(uint32_t*)(gYh + y0 + 8 * nt) = h0;
        *(uint32_t*)(gYl + y0 + 8 * nt) = l0;
        *(uint32_t*)(gYh + y1 + 8 * nt) = h1;
        *(uint32_t*)(gYl + y1 + 8 * nt) = l1;
    }
}

// ============================================================================
// K3: wy = W*y + b via mma.sync, operands pre-split; fused BN partials.
//   grid (2, 64, 4), block 256.
// ============================================================================
__global__ void __launch_bounds__(256) wgemm_mma_kernel(const float* __restrict__ Wb)
{
    extern __shared__ char wsm[];
    const uint32_t smb = smem_u32(wsm);

    const int c0 = blockIdx.x * 128;
    const int n0 = blockIdx.y * 64;
    const int b  = blockIdx.z;
    const int part = blockIdx.y * 4 + blockIdx.z;

    const int tid  = threadIdx.x;
    const int lane = tid & 31;
    const int wrp  = tid >> 5;
    const int qrow = lane >> 2;
    const int qcol = lane & 3;
    const int c    = c0 + 16 * wrp + qrow;

    // stage y planes: 2 x 64 rows x 16 chunks
#pragma unroll
    for (int r = 0; r < 8; r++) {
        int fid = tid + (r << 8);
        int pl = fid >> 10, rem = fid & 1023;
        int row = rem >> 4, ch = rem & 15;
        const __nv_bfloat16* src = (pl ? gYl : gYh) +
            ((size_t)b * HWN + n0 + row) * DN + ch * 8;
        cp16(smb + (pl ? WYL : WYH) + row * 272 + ch * 16, src);
    }
    CP_COMMIT();

    // A fragments direct from pre-split W (L2-hot)
    uint32_t ah[8][4], al[8][4];
#pragma unroll
    for (int ks = 0; ks < 8; ks++) {
        int k = 16 * ks + 2 * qcol;
        ah[ks][0] = *(const uint32_t*)(gWWh + (size_t)c * DN + k);
        ah[ks][1] = *(const uint32_t*)(gWWh + (size_t)(c + 8) * DN + k);
        ah[ks][2] = *(const uint32_t*)(gWWh + (size_t)c * DN + k + 8);
        ah[ks][3] = *(const uint32_t*)(gWWh + (size_t)(c + 8) * DN + k + 8);
        al[ks][0] = *(const uint32_t*)(gWWl + (size_t)c * DN + k);
        al[ks][1] = *(const uint32_t*)(gWWl + (size_t)(c + 8) * DN + k);
        al[ks][2] = *(const uint32_t*)(gWWl + (size_t)c * DN + k + 8);
        al[ks][3] = *(const uint32_t*)(gWWl + (size_t)(c + 8) * DN + k + 8);
    }
    CP_WAIT0();
    __syncthreads();

    float acc[8][4];
#pragma unroll
    for (int i = 0; i < 8; i++)
#pragma unroll
        for (int j = 0; j < 4; j++) acc[i][j] = 0.f;

#pragma unroll
    for (int ks = 0; ks < 8; ks++) {
#pragma unroll
        for (int nt = 0; nt < 8; nt++) {
            uint32_t ro = (8 * nt + qrow) * 272 + 32 * ks + 4 * qcol;
            uint32_t bh0 = lds32(smb + WYH + ro);
            uint32_t bh1 = lds32(smb + WYH + ro + 16);
            uint32_t bl0 = lds32(smb + WYL + ro);
            uint32_t bl1 = lds32(smb + WYL + ro + 16);
            mma_bf16(acc[nt][0], acc[nt][1], acc[nt][2], acc[nt][3],
                     ah[ks][0], ah[ks][1], ah[ks][2], ah[ks][3], bh0, bh1);
            mma_bf16(acc[nt][0], acc[nt][1], acc[nt][2], acc[nt][3],
                     ah[ks][0], ah[ks][1], ah[ks][2], ah[ks][3], bl0, bl1);
            mma_bf16(acc[nt][0], acc[nt][1], acc[nt][2], acc[nt][3],
                     al[ks][0], al[ks][1], al[ks][2], al[ks][3], bh0, bh1);
        }
    }

    float bb0 = Wb[c], bb1 = Wb[c + 8];
    float s0 = 0.f, q0 = 0.f, s1 = 0.f, q1 = 0.f;
#pragma unroll
    for (int nt = 0; nt < 8; nt++) {
        int n = n0 + 8 * nt + 2 * qcol;
        float v0 = acc[nt][0] + bb0, v1 = acc[nt][1] + bb0;
        float v2 = acc[nt][2] + bb1, v3 = acc[nt][3] + bb1;
        s0 += v0 + v1; q0 += v0 * v0 + v1 * v1;
        s1 += v2 + v3; q1 += v2 * v2 + v3 * v3;
        *(float2*)(d_WY + ((size_t)b * CN + c) * HWN + n)     = make_float2(v0, v1);
        *(float2*)(d_WY + ((size_t)b * CN + c + 8) * HWN + n) = make_float2(v2, v3);
    }
    s0 += __shfl_xor_sync(0xffffffffu, s0, 1);
    s0 += __shfl_xor_sync(0xffffffffu, s0, 2);
    q0 += __shfl_xor_sync(0xffffffffu, q0, 1);
    q0 += __shfl_xor_sync(0xffffffffu, q0, 2);
    s1 += __shfl_xor_sync(0xffffffffu, s1, 1);
    s1 += __shfl_xor_sync(0xffffffffu, s1, 2);
    q1 += __shfl_xor_sync(0xffffffffu, q1, 1);
    q1 += __shfl_xor_sync(0xffffffffu, q1, 2);
    if (qcol == 0) {
        gPS[c * 256 + part] = s0;
        gPQ[c * 256 + part] = q0;
        gPS[(c + 8) * 256 + part] = s1;
        gPQ[(c + 8) * 256 + part] = q1;
    }
}

// ============================================================================
// K4: BN stats finalize
// ============================================================================
__global__ void bnfinal_kernel()
{
    const int c = blockIdx.x;
    const int tid = threadIdx.x;
    __shared__ float sh[256], sh2[256];
    sh[tid]  = gPS[c * 256 + tid];
    sh2[tid] = gPQ[c * 256 + tid];
    __syncthreads();
    for (int off = 128; off > 0; off >>= 1) {
        if (tid < off) { sh[tid] += sh[tid + off]; sh2[tid] += sh2[tid + off]; }
        __syncthreads();
    }
    if (tid == 0) {
        const float invN = 1.f / (float)(BN * HWN);
        float mean = sh[0] * invN;
        float var  = sh2[0] * invN - mean * mean;
        d_MEAN[c] = mean;
        d_RSTD[c] = rsqrtf(var + 1e-5f);
    }
}

// ============================================================================
// K5: finalize
// ============================================================================
__global__ void finalize_kernel(const float* __restrict__ x,
                                const float* __restrict__ gamma,
                                const float* __restrict__ beta,
                                float* __restrict__ out)
{
    int idx = blockIdx.x * blockDim.x + threadIdx.x;
    int c = (idx >> 10) & 255;
    float4 wv = ((const float4*)d_WY)[idx];
    float4 xv = ((const float4*)x)[idx];
    float g  = gamma[c] * d_RSTD[c];
    float m  = d_MEAN[c];
    float bt = beta[c];
    float4 o;
    o.x = (wv.x - m) * g + bt + xv.x;
    o.y = (wv.y - m) * g + bt + xv.y;
    o.z = (wv.z - m) * g + bt + xv.z;
    o.w = (wv.w - m) * g + bt + xv.w;
    ((float4*)out)[idx] = o;
}

// ============================================================================
extern "C" void kernel_launch(void* const* d_in, const int* in_sizes, int n_in,
                              void* d_out, int out_size)
{
    const float* x     = (const float*)d_in[0];
    const float* tw    = (const float*)d_in[1];
    const float* tb    = (const float*)d_in[2];
    const float* pw    = (const float*)d_in[3];
    const float* pb    = (const float*)d_in[4];
    const float* gw    = (const float*)d_in[5];
    const float* gb    = (const float*)d_in[6];
    const float* Ww    = (const float*)d_in[7];
    const float* Wb    = (const float*)d_in[8];
    const float* gamma = (const float*)d_in[9];
    const float* beta  = (const float*)d_in[10];
    float* out = (float*)d_out;

    cudaFuncSetAttribute(proj_mma_kernel, cudaFuncAttributeMaxDynamicSharedMemorySize, PRJ_SMEM);
    cudaFuncSetAttribute(attn_mma_kernel, cudaFuncAttributeMaxDynamicSharedMemorySize, ATTN_SMEM);
    cudaFuncSetAttribute(wgemm_mma_kernel, cudaFuncAttributeMaxDynamicSharedMemorySize, WG_SMEM);

    wsplit_kernel<<<256, 256>>>(tw, pw, gw, Ww);

    dim3 gx(HWN / 64, CN / 64, BN);
    xsplit_kernel<<<gx, 256>>>(x);

    dim3 g1(3, HWN / 64, BN);
    proj_mma_kernel<<<g1, 256, PRJ_SMEM>>>(tb, pb, gb);

    dim3 g2(HWN / TM, BN);
    attn_mma_kernel<<<g2, 256, ATTN_SMEM>>>();

    dim3 g3(2, HWN / 64, BN);
    wgemm_mma_kernel<<<g3, 256, WG_SMEM>>>(Wb);

    bnfinal_kernel<<<CN, 256>>>();

    finalize_kernel<<<(BN * CN * HWN / 4) / 256, 256>>>(x, gamma, beta, out);
}